// round 1
// baseline (speedup 1.0000x reference)
#include <cuda_runtime.h>
#include <math.h>

#define S_LEN 2048
#define E_DIM 1024
#define H_DIM 1024
#define V_DIM 32000
#define EH    2048   // E+H

// ---------------- scratch (no allocations allowed) ----------------
__device__ float d_h[H_DIM];
__device__ float d_c[H_DIM];
__device__ float d_t[H_DIM];        // W_att[:, :H] @ h + b_att
__device__ float d_scores[S_LEN];
__device__ float d_wbuf[S_LEN];
__device__ float d_ctx[E_DIM];
__device__ float d_xt[H_DIM];
__device__ float d_logits[V_DIM];
__device__ float d_red[2];          // [0]=max logit, [1]=sum exp

__device__ __forceinline__ void atomicMaxFloat(float* addr, float val) {
    if (val >= 0.0f) atomicMax((int*)addr, __float_as_int(val));
    else             atomicMin((unsigned int*)addr, __float_as_uint(val));
}

__device__ __forceinline__ float sigmoidf(float x) { return 1.0f / (1.0f + expf(-x)); }

// ---------------- K1: LSTM step -> h, c ----------------
// warp per hidden unit j; 4 gate rows each
__global__ void lstm_kernel(const int* __restrict__ word_input,
                            const float* __restrict__ last_ctx,
                            const float* __restrict__ h0,
                            const float* __restrict__ c0,
                            const float* __restrict__ emb,
                            const float* __restrict__ W_ih,
                            const float* __restrict__ b_ih,
                            const float* __restrict__ W_hh,
                            const float* __restrict__ b_hh,
                            float* out_h, float* out_c)
{
    __shared__ float sin_[EH + H_DIM];  // [lstm_in(2048) | h_prev(1024)]
    int tid = threadIdx.x;
    int word = word_input[0];
    for (int i = tid; i < H_DIM; i += blockDim.x) {
        sin_[i]          = last_ctx[i];
        sin_[H_DIM + i]  = emb[(size_t)word * E_DIM + i];
        sin_[EH + i]     = h0[i];
    }
    __syncthreads();

    int warp = blockIdx.x * (blockDim.x >> 5) + (tid >> 5);
    int lane = tid & 31;
    if (warp >= H_DIM) return;
    int j = warp;

    float acc0 = 0.f, acc1 = 0.f, acc2 = 0.f, acc3 = 0.f;
    const float* r0 = W_ih + (size_t)(j           ) * EH;
    const float* r1 = W_ih + (size_t)(j +   H_DIM ) * EH;
    const float* r2 = W_ih + (size_t)(j + 2*H_DIM ) * EH;
    const float* r3 = W_ih + (size_t)(j + 3*H_DIM ) * EH;
    for (int k = lane * 4; k < EH; k += 128) {
        float4 x = *(const float4*)&sin_[k];
        float4 w;
        w = *(const float4*)&r0[k]; acc0 += w.x*x.x + w.y*x.y + w.z*x.z + w.w*x.w;
        w = *(const float4*)&r1[k]; acc1 += w.x*x.x + w.y*x.y + w.z*x.z + w.w*x.w;
        w = *(const float4*)&r2[k]; acc2 += w.x*x.x + w.y*x.y + w.z*x.z + w.w*x.w;
        w = *(const float4*)&r3[k]; acc3 += w.x*x.x + w.y*x.y + w.z*x.z + w.w*x.w;
    }
    r0 = W_hh + (size_t)(j           ) * H_DIM;
    r1 = W_hh + (size_t)(j +   H_DIM ) * H_DIM;
    r2 = W_hh + (size_t)(j + 2*H_DIM ) * H_DIM;
    r3 = W_hh + (size_t)(j + 3*H_DIM ) * H_DIM;
    for (int k = lane * 4; k < H_DIM; k += 128) {
        float4 x = *(const float4*)&sin_[EH + k];
        float4 w;
        w = *(const float4*)&r0[k]; acc0 += w.x*x.x + w.y*x.y + w.z*x.z + w.w*x.w;
        w = *(const float4*)&r1[k]; acc1 += w.x*x.x + w.y*x.y + w.z*x.z + w.w*x.w;
        w = *(const float4*)&r2[k]; acc2 += w.x*x.x + w.y*x.y + w.z*x.z + w.w*x.w;
        w = *(const float4*)&r3[k]; acc3 += w.x*x.x + w.y*x.y + w.z*x.z + w.w*x.w;
    }
    #pragma unroll
    for (int off = 16; off; off >>= 1) {
        acc0 += __shfl_down_sync(0xffffffffu, acc0, off);
        acc1 += __shfl_down_sync(0xffffffffu, acc1, off);
        acc2 += __shfl_down_sync(0xffffffffu, acc2, off);
        acc3 += __shfl_down_sync(0xffffffffu, acc3, off);
    }
    if (lane == 0) {
        float gi = acc0 + b_ih[j]           + b_hh[j];
        float gf = acc1 + b_ih[j +   H_DIM] + b_hh[j +   H_DIM];
        float gg = acc2 + b_ih[j + 2*H_DIM] + b_hh[j + 2*H_DIM];
        float go = acc3 + b_ih[j + 3*H_DIM] + b_hh[j + 3*H_DIM];
        float iv = sigmoidf(gi);
        float fv = sigmoidf(gf);
        float gv = tanhf(gg);
        float ov = sigmoidf(go);
        float cv = fv * c0[j] + iv * gv;
        float hv = ov * tanhf(cv);
        d_h[j] = hv; d_c[j] = cv;
        if (out_h) out_h[j] = hv;
        if (out_c) out_c[j] = cv;
    }
}

// ---------------- K2: t_j = W_att[j, :H] . h + b_att[j] ----------------
__global__ void hterm_kernel(const float* __restrict__ W_att,
                             const float* __restrict__ b_att)
{
    __shared__ float sh[H_DIM];
    int tid = threadIdx.x;
    for (int i = tid; i < H_DIM; i += blockDim.x) sh[i] = d_h[i];
    __syncthreads();
    int warp = blockIdx.x * (blockDim.x >> 5) + (tid >> 5);
    int lane = tid & 31;
    if (warp >= H_DIM) return;
    const float* row = W_att + (size_t)warp * EH;
    float acc = 0.f;
    for (int k = lane * 4; k < H_DIM; k += 128) {
        float4 w = *(const float4*)&row[k];
        float4 x = *(const float4*)&sh[k];
        acc += w.x*x.x + w.y*x.y + w.z*x.z + w.w*x.w;
    }
    #pragma unroll
    for (int off = 16; off; off >>= 1) acc += __shfl_down_sync(0xffffffffu, acc, off);
    if (lane == 0) d_t[warp] = acc + b_att[warp];
}

// ---------------- K3: scores GEMM (fused tanh + v reduction) ----------------
// scores[s] = sum_j v[j] * tanh( enc[s,:] . W_att[j, H:] + t[j] )
#define BM 64
#define BN 64
#define BK 16
__global__ void scores_kernel(const float* __restrict__ enc,
                              const float* __restrict__ W_att,
                              const float* __restrict__ v)
{
    __shared__ float As[BM][BK];
    __shared__ float Bs[BK][BN + 4];
    int tid = threadIdx.x;
    int tx = tid & 15, ty = tid >> 4;        // 16x16 threads, 4x4 each
    int m0 = blockIdx.x * BM;
    int lr = tid >> 2;                       // 0..63
    int lc = (tid & 3) * 4;                  // 0,4,8,12

    float msc0 = 0.f, msc1 = 0.f, msc2 = 0.f, msc3 = 0.f;

    for (int nt = 0; nt < H_DIM / BN; nt++) {
        int n0 = nt * BN;
        float acc[4][4];
        #pragma unroll
        for (int i = 0; i < 4; i++)
            #pragma unroll
            for (int jj = 0; jj < 4; jj++) acc[i][jj] = 0.f;

        for (int kt = 0; kt < E_DIM; kt += BK) {
            float4 av = *(const float4*)&enc[(size_t)(m0 + lr) * E_DIM + kt + lc];
            *(float4*)&As[lr][lc] = av;
            float4 bv = *(const float4*)&W_att[(size_t)(n0 + lr) * EH + H_DIM + kt + lc];
            Bs[lc + 0][lr] = bv.x;
            Bs[lc + 1][lr] = bv.y;
            Bs[lc + 2][lr] = bv.z;
            Bs[lc + 3][lr] = bv.w;
            __syncthreads();
            #pragma unroll
            for (int kk = 0; kk < BK; kk++) {
                float a0 = As[ty*4 + 0][kk];
                float a1 = As[ty*4 + 1][kk];
                float a2 = As[ty*4 + 2][kk];
                float a3 = As[ty*4 + 3][kk];
                float4 b = *(const float4*)&Bs[kk][tx*4];
                acc[0][0] += a0*b.x; acc[0][1] += a0*b.y; acc[0][2] += a0*b.z; acc[0][3] += a0*b.w;
                acc[1][0] += a1*b.x; acc[1][1] += a1*b.y; acc[1][2] += a1*b.z; acc[1][3] += a1*b.w;
                acc[2][0] += a2*b.x; acc[2][1] += a2*b.y; acc[2][2] += a2*b.z; acc[2][3] += a2*b.w;
                acc[3][0] += a3*b.x; acc[3][1] += a3*b.y; acc[3][2] += a3*b.z; acc[3][3] += a3*b.w;
            }
            __syncthreads();
        }
        // epilogue: fold this N tile into per-row score partials
        #pragma unroll
        for (int jj = 0; jj < 4; jj++) {
            int n = n0 + tx*4 + jj;
            float tn = d_t[n];
            float vn = v[n];
            msc0 += vn * tanhf(acc[0][jj] + tn);
            msc1 += vn * tanhf(acc[1][jj] + tn);
            msc2 += vn * tanhf(acc[2][jj] + tn);
            msc3 += vn * tanhf(acc[3][jj] + tn);
        }
    }
    // reduce across the 16 tx lanes (width-16 shuffle groups == tx groups)
    #pragma unroll
    for (int off = 8; off; off >>= 1) {
        msc0 += __shfl_down_sync(0xffffffffu, msc0, off, 16);
        msc1 += __shfl_down_sync(0xffffffffu, msc1, off, 16);
        msc2 += __shfl_down_sync(0xffffffffu, msc2, off, 16);
        msc3 += __shfl_down_sync(0xffffffffu, msc3, off, 16);
    }
    if (tx == 0) {
        d_scores[m0 + ty*4 + 0] = msc0;
        d_scores[m0 + ty*4 + 1] = msc1;
        d_scores[m0 + ty*4 + 2] = msc2;
        d_scores[m0 + ty*4 + 3] = msc3;
    }
}

// ---------------- K4: softmax over scores (single block) ----------------
__global__ void softmax_kernel(float* out_w)
{
    __shared__ float red[256];
    __shared__ float smax, ssum;
    int tid = threadIdx.x;
    float m = -1e30f;
    for (int i = tid; i < S_LEN; i += 256) m = fmaxf(m, d_scores[i]);
    red[tid] = m; __syncthreads();
    for (int off = 128; off; off >>= 1) {
        if (tid < off) red[tid] = fmaxf(red[tid], red[tid + off]);
        __syncthreads();
    }
    if (tid == 0) smax = red[0];
    __syncthreads();
    float sum = 0.f;
    for (int i = tid; i < S_LEN; i += 256) sum += expf(d_scores[i] - smax);
    red[tid] = sum; __syncthreads();
    for (int off = 128; off; off >>= 1) {
        if (tid < off) red[tid] += red[tid + off];
        __syncthreads();
    }
    if (tid == 0) ssum = red[0];
    __syncthreads();
    float inv = 1.0f / ssum;
    for (int i = tid; i < S_LEN; i += 256) {
        float w = expf(d_scores[i] - smax) * inv;
        d_wbuf[i] = w;
        if (out_w) out_w[i] = w;
    }
    for (int i = tid; i < E_DIM; i += 256) d_ctx[i] = 0.f;  // zero for K5 atomics
}

// ---------------- K5: context = w @ enc ----------------
__global__ void context_kernel(const float* __restrict__ enc)
{
    int e  = blockIdx.y * 256 + threadIdx.x;
    int s0 = blockIdx.x * 128;
    float acc = 0.f;
    for (int s = s0; s < s0 + 128; s++)
        acc += d_wbuf[s] * enc[(size_t)s * E_DIM + e];
    atomicAdd(&d_ctx[e], acc);
}

// ---------------- K6: x_t = tanh(W_ah @ [context; h] + b_ah) ----------------
__global__ void xt_kernel(const float* __restrict__ W_ah,
                          const float* __restrict__ b_ah,
                          float* out_xt)
{
    __shared__ float cat[EH];
    int tid = threadIdx.x;
    for (int i = tid; i < H_DIM; i += blockDim.x) {
        cat[i]          = d_ctx[i];
        cat[H_DIM + i]  = d_h[i];
    }
    __syncthreads();
    if (blockIdx.x == 0 && tid == 0) { d_red[0] = -1e30f; d_red[1] = 0.f; }
    int warp = blockIdx.x * (blockDim.x >> 5) + (tid >> 5);
    int lane = tid & 31;
    if (warp >= H_DIM) return;
    const float* row = W_ah + (size_t)warp * EH;
    float acc = 0.f;
    for (int k = lane * 4; k < EH; k += 128) {
        float4 w = *(const float4*)&row[k];
        float4 x = *(const float4*)&cat[k];
        acc += w.x*x.x + w.y*x.y + w.z*x.z + w.w*x.w;
    }
    #pragma unroll
    for (int off = 16; off; off >>= 1) acc += __shfl_down_sync(0xffffffffu, acc, off);
    if (lane == 0) {
        float x = tanhf(acc + b_ah[warp]);
        d_xt[warp] = x;
        if (out_xt) out_xt[warp] = x;
    }
}

// ---------------- K7: logits = W_out @ x_t + b_out (+ global max) ----------------
__global__ void logits_kernel(const float* __restrict__ W_out,
                              const float* __restrict__ b_out)
{
    __shared__ float sx[H_DIM];
    __shared__ float wmax[8];
    int tid = threadIdx.x;
    for (int i = tid; i < H_DIM; i += 256) sx[i] = d_xt[i];
    __syncthreads();
    int warpl = tid >> 5, lane = tid & 31;
    int row = blockIdx.x * 8 + warpl;
    float lg = -1e30f;
    const float* wr = W_out + (size_t)row * H_DIM;
    float acc = 0.f;
    for (int k = lane * 4; k < H_DIM; k += 128) {
        float4 w = *(const float4*)&wr[k];
        float4 x = *(const float4*)&sx[k];
        acc += w.x*x.x + w.y*x.y + w.z*x.z + w.w*x.w;
    }
    #pragma unroll
    for (int off = 16; off; off >>= 1) acc += __shfl_down_sync(0xffffffffu, acc, off);
    if (lane == 0) {
        lg = acc + b_out[row];
        d_logits[row] = lg;
        wmax[warpl] = lg;
    }
    __syncthreads();
    if (tid == 0) {
        float m = wmax[0];
        #pragma unroll
        for (int i = 1; i < 8; i++) m = fmaxf(m, wmax[i]);
        atomicMaxFloat(&d_red[0], m);
    }
}

// ---------------- K8: sum of exp(logit - max) ----------------
__global__ void sumexp_kernel()
{
    __shared__ float red[256];
    int tid = threadIdx.x;
    float mx = d_red[0];
    float acc = 0.f;
    for (int r = blockIdx.x * 256 + tid; r < V_DIM; r += gridDim.x * 256)
        acc += expf(d_logits[r] - mx);
    red[tid] = acc; __syncthreads();
    for (int off = 128; off; off >>= 1) {
        if (tid < off) red[tid] += red[tid + off];
        __syncthreads();
    }
    if (tid == 0) atomicAdd(&d_red[1], red[0]);
}

// ---------------- K9: out = logits - logsumexp ----------------
__global__ void writeout_kernel(float* __restrict__ out)
{
    float lse = d_red[0] + logf(d_red[1]);
    int r = blockIdx.x * 256 + threadIdx.x;
    if (r < V_DIM) out[r] = d_logits[r] - lse;
}

// ---------------- launch ----------------
extern "C" void kernel_launch(void* const* d_in, const int* in_sizes, int n_in,
                              void* d_out, int out_size)
{
    const float* enc    = (const float*)d_in[0];
    const int*   word   = (const int*)  d_in[1];
    const float* lastc  = (const float*)d_in[2];
    const float* h0     = (const float*)d_in[3];
    const float* c0     = (const float*)d_in[4];
    const float* emb    = (const float*)d_in[5];
    const float* W_ih   = (const float*)d_in[6];
    const float* b_ih   = (const float*)d_in[7];
    const float* W_hh   = (const float*)d_in[8];
    const float* b_hh   = (const float*)d_in[9];
    const float* W_att  = (const float*)d_in[10];
    const float* b_att  = (const float*)d_in[11];
    const float* v      = (const float*)d_in[12];
    const float* W_ah   = (const float*)d_in[13];
    const float* b_ah   = (const float*)d_in[14];
    const float* W_out  = (const float*)d_in[15];
    const float* b_out  = (const float*)d_in[16];
    float* out = (float*)d_out;

    // flattened pytree: [output(V), h(H), c(H), x_t(H), w(S)]
    bool full = (out_size >= V_DIM + 3 * H_DIM + S_LEN);
    float* out_h  = full ? out + V_DIM              : nullptr;
    float* out_c  = full ? out + V_DIM + H_DIM      : nullptr;
    float* out_xt = full ? out + V_DIM + 2 * H_DIM  : nullptr;
    float* out_w  = full ? out + V_DIM + 3 * H_DIM  : nullptr;

    lstm_kernel   <<<128, 256>>>(word, lastc, h0, c0, emb, W_ih, b_ih, W_hh, b_hh, out_h, out_c);
    hterm_kernel  <<<128, 256>>>(W_att, b_att);
    scores_kernel <<<S_LEN / BM, 256>>>(enc, W_att, v);
    softmax_kernel<<<1, 256>>>(out_w);
    context_kernel<<<dim3(16, 4), 256>>>(enc);
    xt_kernel     <<<128, 256>>>(W_ah, b_ah, out_xt);
    logits_kernel <<<V_DIM / 8, 256>>>(W_out, b_out);
    sumexp_kernel <<<32, 256>>>();
    writeout_kernel<<<125, 256>>>(out);
}

// round 2
// speedup vs baseline: 4.0036x; 4.0036x over previous
#include <cuda_runtime.h>
#include <math.h>

#define S_LEN 2048
#define E_DIM 1024
#define H_DIM 1024
#define V_DIM 32000
#define EH    2048   // E+H
#define NT    16     // number of N tiles in scores GEMM

// ---------------- scratch (no allocations allowed) ----------------
__device__ float d_h[H_DIM];
__device__ float d_c[H_DIM];
__device__ float d_t[H_DIM];           // W_att[:, :H] @ h + b_att
__device__ float d_part[NT][S_LEN];    // partial scores per n-tile
__device__ float d_wbuf[S_LEN];
__device__ float d_ctx[E_DIM];
__device__ float d_xt[H_DIM];
__device__ float d_logits[V_DIM];
__device__ float d_red[2];             // [0]=max logit, [1]=sum exp

__device__ __forceinline__ void atomicMaxFloat(float* addr, float val) {
    if (val >= 0.0f) atomicMax((int*)addr, __float_as_int(val));
    else             atomicMin((unsigned int*)addr, __float_as_uint(val));
}

__device__ __forceinline__ float sigmoidf(float x) { return 1.0f / (1.0f + expf(-x)); }

// ---------------- K1: LSTM step -> h, c ----------------
__global__ void lstm_kernel(const int* __restrict__ word_input,
                            const float* __restrict__ last_ctx,
                            const float* __restrict__ h0,
                            const float* __restrict__ c0,
                            const float* __restrict__ emb,
                            const float* __restrict__ W_ih,
                            const float* __restrict__ b_ih,
                            const float* __restrict__ W_hh,
                            const float* __restrict__ b_hh,
                            float* out_h, float* out_c)
{
    __shared__ float sin_[EH + H_DIM];  // [lstm_in(2048) | h_prev(1024)]
    int tid = threadIdx.x;
    int word = word_input[0];
    for (int i = tid; i < H_DIM; i += blockDim.x) {
        sin_[i]          = last_ctx[i];
        sin_[H_DIM + i]  = emb[(size_t)word * E_DIM + i];
        sin_[EH + i]     = h0[i];
    }
    __syncthreads();

    int warp = blockIdx.x * (blockDim.x >> 5) + (tid >> 5);
    int lane = tid & 31;
    if (warp >= H_DIM) return;
    int j = warp;

    float acc0 = 0.f, acc1 = 0.f, acc2 = 0.f, acc3 = 0.f;
    const float* r0 = W_ih + (size_t)(j           ) * EH;
    const float* r1 = W_ih + (size_t)(j +   H_DIM ) * EH;
    const float* r2 = W_ih + (size_t)(j + 2*H_DIM ) * EH;
    const float* r3 = W_ih + (size_t)(j + 3*H_DIM ) * EH;
    for (int k = lane * 4; k < EH; k += 128) {
        float4 x = *(const float4*)&sin_[k];
        float4 w;
        w = *(const float4*)&r0[k]; acc0 += w.x*x.x + w.y*x.y + w.z*x.z + w.w*x.w;
        w = *(const float4*)&r1[k]; acc1 += w.x*x.x + w.y*x.y + w.z*x.z + w.w*x.w;
        w = *(const float4*)&r2[k]; acc2 += w.x*x.x + w.y*x.y + w.z*x.z + w.w*x.w;
        w = *(const float4*)&r3[k]; acc3 += w.x*x.x + w.y*x.y + w.z*x.z + w.w*x.w;
    }
    r0 = W_hh + (size_t)(j           ) * H_DIM;
    r1 = W_hh + (size_t)(j +   H_DIM ) * H_DIM;
    r2 = W_hh + (size_t)(j + 2*H_DIM ) * H_DIM;
    r3 = W_hh + (size_t)(j + 3*H_DIM ) * H_DIM;
    for (int k = lane * 4; k < H_DIM; k += 128) {
        float4 x = *(const float4*)&sin_[EH + k];
        float4 w;
        w = *(const float4*)&r0[k]; acc0 += w.x*x.x + w.y*x.y + w.z*x.z + w.w*x.w;
        w = *(const float4*)&r1[k]; acc1 += w.x*x.x + w.y*x.y + w.z*x.z + w.w*x.w;
        w = *(const float4*)&r2[k]; acc2 += w.x*x.x + w.y*x.y + w.z*x.z + w.w*x.w;
        w = *(const float4*)&r3[k]; acc3 += w.x*x.x + w.y*x.y + w.z*x.z + w.w*x.w;
    }
    #pragma unroll
    for (int off = 16; off; off >>= 1) {
        acc0 += __shfl_down_sync(0xffffffffu, acc0, off);
        acc1 += __shfl_down_sync(0xffffffffu, acc1, off);
        acc2 += __shfl_down_sync(0xffffffffu, acc2, off);
        acc3 += __shfl_down_sync(0xffffffffu, acc3, off);
    }
    if (lane == 0) {
        float gi = acc0 + b_ih[j]           + b_hh[j];
        float gf = acc1 + b_ih[j +   H_DIM] + b_hh[j +   H_DIM];
        float gg = acc2 + b_ih[j + 2*H_DIM] + b_hh[j + 2*H_DIM];
        float go = acc3 + b_ih[j + 3*H_DIM] + b_hh[j + 3*H_DIM];
        float iv = sigmoidf(gi);
        float fv = sigmoidf(gf);
        float gv = tanhf(gg);
        float ov = sigmoidf(go);
        float cv = fv * c0[j] + iv * gv;
        float hv = ov * tanhf(cv);
        d_h[j] = hv; d_c[j] = cv;
        if (out_h) out_h[j] = hv;
        if (out_c) out_c[j] = cv;
    }
}

// ---------------- K2: t_j = W_att[j, :H] . h + b_att[j] ----------------
__global__ void hterm_kernel(const float* __restrict__ W_att,
                             const float* __restrict__ b_att)
{
    __shared__ float sh[H_DIM];
    int tid = threadIdx.x;
    for (int i = tid; i < H_DIM; i += blockDim.x) sh[i] = d_h[i];
    __syncthreads();
    int warp = blockIdx.x * (blockDim.x >> 5) + (tid >> 5);
    int lane = tid & 31;
    if (warp >= H_DIM) return;
    const float* row = W_att + (size_t)warp * EH;
    float acc = 0.f;
    for (int k = lane * 4; k < H_DIM; k += 128) {
        float4 w = *(const float4*)&row[k];
        float4 x = *(const float4*)&sh[k];
        acc += w.x*x.x + w.y*x.y + w.z*x.z + w.w*x.w;
    }
    #pragma unroll
    for (int off = 16; off; off >>= 1) acc += __shfl_down_sync(0xffffffffu, acc, off);
    if (lane == 0) d_t[warp] = acc + b_att[warp];
}

// ---------------- K3: scores GEMM partials (fused tanh + v reduction) ----------------
// block (nt, mt): d_part[nt][s] = sum_{n in tile nt} v[n] * tanh( enc[s,:] . W_att[n, H:] + t[n] )
#define BM 64
#define BN 64
#define BK 16
__global__ void scores_kernel(const float* __restrict__ enc,
                              const float* __restrict__ W_att,
                              const float* __restrict__ v)
{
    __shared__ float As[BM][BK];
    __shared__ float Bs[BK][BN + 4];
    int tid = threadIdx.x;
    int tx = tid & 15, ty = tid >> 4;        // 16x16 threads, 4x4 each
    int m0 = blockIdx.y * BM;
    int n0 = blockIdx.x * BN;
    int lr = tid >> 2;                       // 0..63
    int lc = (tid & 3) * 4;                  // 0,4,8,12

    float acc[4][4];
    #pragma unroll
    for (int i = 0; i < 4; i++)
        #pragma unroll
        for (int jj = 0; jj < 4; jj++) acc[i][jj] = 0.f;

    for (int kt = 0; kt < E_DIM; kt += BK) {
        float4 av = *(const float4*)&enc[(size_t)(m0 + lr) * E_DIM + kt + lc];
        *(float4*)&As[lr][lc] = av;
        float4 bv = *(const float4*)&W_att[(size_t)(n0 + lr) * EH + H_DIM + kt + lc];
        Bs[lc + 0][lr] = bv.x;
        Bs[lc + 1][lr] = bv.y;
        Bs[lc + 2][lr] = bv.z;
        Bs[lc + 3][lr] = bv.w;
        __syncthreads();
        #pragma unroll
        for (int kk = 0; kk < BK; kk++) {
            float a0 = As[ty*4 + 0][kk];
            float a1 = As[ty*4 + 1][kk];
            float a2 = As[ty*4 + 2][kk];
            float a3 = As[ty*4 + 3][kk];
            float4 b = *(const float4*)&Bs[kk][tx*4];
            acc[0][0] += a0*b.x; acc[0][1] += a0*b.y; acc[0][2] += a0*b.z; acc[0][3] += a0*b.w;
            acc[1][0] += a1*b.x; acc[1][1] += a1*b.y; acc[1][2] += a1*b.z; acc[1][3] += a1*b.w;
            acc[2][0] += a2*b.x; acc[2][1] += a2*b.y; acc[2][2] += a2*b.z; acc[2][3] += a2*b.w;
            acc[3][0] += a3*b.x; acc[3][1] += a3*b.y; acc[3][2] += a3*b.z; acc[3][3] += a3*b.w;
        }
        __syncthreads();
    }

    // epilogue: fold N tile into per-row partial scores
    float msc0 = 0.f, msc1 = 0.f, msc2 = 0.f, msc3 = 0.f;
    #pragma unroll
    for (int jj = 0; jj < 4; jj++) {
        int n = n0 + tx*4 + jj;
        float tn = d_t[n];
        float vn = v[n];
        msc0 += vn * tanhf(acc[0][jj] + tn);
        msc1 += vn * tanhf(acc[1][jj] + tn);
        msc2 += vn * tanhf(acc[2][jj] + tn);
        msc3 += vn * tanhf(acc[3][jj] + tn);
    }
    // reduce across the 16 tx lanes
    #pragma unroll
    for (int off = 8; off; off >>= 1) {
        msc0 += __shfl_down_sync(0xffffffffu, msc0, off, 16);
        msc1 += __shfl_down_sync(0xffffffffu, msc1, off, 16);
        msc2 += __shfl_down_sync(0xffffffffu, msc2, off, 16);
        msc3 += __shfl_down_sync(0xffffffffu, msc3, off, 16);
    }
    if (tx == 0) {
        d_part[blockIdx.x][m0 + ty*4 + 0] = msc0;
        d_part[blockIdx.x][m0 + ty*4 + 1] = msc1;
        d_part[blockIdx.x][m0 + ty*4 + 2] = msc2;
        d_part[blockIdx.x][m0 + ty*4 + 3] = msc3;
    }
}

// ---------------- K4: fold partials + softmax (single block, 1024 thr) ----------------
__global__ void softmax_kernel(float* out_w)
{
    __shared__ float red[32];
    __shared__ float sc[S_LEN];
    __shared__ float smax, ssum;
    int tid = threadIdx.x;
    int lane = tid & 31, warp = tid >> 5;

    float m = -1e30f;
    for (int i = tid; i < S_LEN; i += 1024) {
        float s = 0.f;
        #pragma unroll
        for (int p = 0; p < NT; p++) s += d_part[p][i];
        sc[i] = s;
        m = fmaxf(m, s);
    }
    #pragma unroll
    for (int off = 16; off; off >>= 1) m = fmaxf(m, __shfl_xor_sync(0xffffffffu, m, off));
    if (lane == 0) red[warp] = m;
    __syncthreads();
    if (warp == 0) {
        m = red[lane];
        #pragma unroll
        for (int off = 16; off; off >>= 1) m = fmaxf(m, __shfl_xor_sync(0xffffffffu, m, off));
        if (lane == 0) smax = m;
    }
    __syncthreads();
    float mx = smax;
    float sum = 0.f;
    for (int i = tid; i < S_LEN; i += 1024) sum += expf(sc[i] - mx);
    #pragma unroll
    for (int off = 16; off; off >>= 1) sum += __shfl_xor_sync(0xffffffffu, sum, off);
    if (lane == 0) red[warp] = sum;
    __syncthreads();
    if (warp == 0) {
        sum = red[lane];
        #pragma unroll
        for (int off = 16; off; off >>= 1) sum += __shfl_xor_sync(0xffffffffu, sum, off);
        if (lane == 0) ssum = sum;
    }
    __syncthreads();
    float inv = 1.0f / ssum;
    for (int i = tid; i < S_LEN; i += 1024) {
        float w = expf(sc[i] - mx) * inv;
        d_wbuf[i] = w;
        if (out_w) out_w[i] = w;
    }
    for (int i = tid; i < E_DIM; i += 1024) d_ctx[i] = 0.f;  // zero for K5 atomics
}

// ---------------- K5: context = w @ enc ----------------
__global__ void context_kernel(const float* __restrict__ enc)
{
    int e  = blockIdx.y * 256 + threadIdx.x;
    int s0 = blockIdx.x * 128;
    float acc = 0.f;
    for (int s = s0; s < s0 + 128; s++)
        acc += d_wbuf[s] * enc[(size_t)s * E_DIM + e];
    atomicAdd(&d_ctx[e], acc);
}

// ---------------- K6: x_t = tanh(W_ah @ [context; h] + b_ah) ----------------
__global__ void xt_kernel(const float* __restrict__ W_ah,
                          const float* __restrict__ b_ah,
                          float* out_xt)
{
    __shared__ float cat[EH];
    int tid = threadIdx.x;
    for (int i = tid; i < H_DIM; i += blockDim.x) {
        cat[i]          = d_ctx[i];
        cat[H_DIM + i]  = d_h[i];
    }
    __syncthreads();
    if (blockIdx.x == 0 && tid == 0) { d_red[0] = -1e30f; d_red[1] = 0.f; }
    int warp = blockIdx.x * (blockDim.x >> 5) + (tid >> 5);
    int lane = tid & 31;
    if (warp >= H_DIM) return;
    const float* row = W_ah + (size_t)warp * EH;
    float acc = 0.f;
    for (int k = lane * 4; k < EH; k += 128) {
        float4 w = *(const float4*)&row[k];
        float4 x = *(const float4*)&cat[k];
        acc += w.x*x.x + w.y*x.y + w.z*x.z + w.w*x.w;
    }
    #pragma unroll
    for (int off = 16; off; off >>= 1) acc += __shfl_down_sync(0xffffffffu, acc, off);
    if (lane == 0) {
        float x = tanhf(acc + b_ah[warp]);
        d_xt[warp] = x;
        if (out_xt) out_xt[warp] = x;
    }
}

// ---------------- K7: logits = W_out @ x_t + b_out (+ global max) ----------------
__global__ void logits_kernel(const float* __restrict__ W_out,
                              const float* __restrict__ b_out)
{
    __shared__ float sx[H_DIM];
    __shared__ float wmax[8];
    int tid = threadIdx.x;
    for (int i = tid; i < H_DIM; i += 256) sx[i] = d_xt[i];
    __syncthreads();
    int warpl = tid >> 5, lane = tid & 31;
    int row = blockIdx.x * 8 + warpl;
    const float* wr = W_out + (size_t)row * H_DIM;
    float acc = 0.f;
    for (int k = lane * 4; k < H_DIM; k += 128) {
        float4 w = *(const float4*)&wr[k];
        float4 x = *(const float4*)&sx[k];
        acc += w.x*x.x + w.y*x.y + w.z*x.z + w.w*x.w;
    }
    #pragma unroll
    for (int off = 16; off; off >>= 1) acc += __shfl_down_sync(0xffffffffu, acc, off);
    if (lane == 0) {
        float lg = acc + b_out[row];
        d_logits[row] = lg;
        wmax[warpl] = lg;
    }
    __syncthreads();
    if (tid == 0) {
        float m = wmax[0];
        #pragma unroll
        for (int i = 1; i < 8; i++) m = fmaxf(m, wmax[i]);
        atomicMaxFloat(&d_red[0], m);
    }
}

// ---------------- K8: sum of exp(logit - max) ----------------
__global__ void sumexp_kernel()
{
    __shared__ float red[256];
    int tid = threadIdx.x;
    float mx = d_red[0];
    float acc = 0.f;
    for (int r = blockIdx.x * 256 + tid; r < V_DIM; r += gridDim.x * 256)
        acc += expf(d_logits[r] - mx);
    red[tid] = acc; __syncthreads();
    for (int off = 128; off; off >>= 1) {
        if (tid < off) red[tid] += red[tid + off];
        __syncthreads();
    }
    if (tid == 0) atomicAdd(&d_red[1], red[0]);
}

// ---------------- K9: out = logits - logsumexp ----------------
__global__ void writeout_kernel(float* __restrict__ out)
{
    float lse = d_red[0] + logf(d_red[1]);
    int r = blockIdx.x * 256 + threadIdx.x;
    if (r < V_DIM) out[r] = d_logits[r] - lse;
}

// ---------------- launch ----------------
extern "C" void kernel_launch(void* const* d_in, const int* in_sizes, int n_in,
                              void* d_out, int out_size)
{
    const float* enc    = (const float*)d_in[0];
    const int*   word   = (const int*)  d_in[1];
    const float* lastc  = (const float*)d_in[2];
    const float* h0     = (const float*)d_in[3];
    const float* c0     = (const float*)d_in[4];
    const float* emb    = (const float*)d_in[5];
    const float* W_ih   = (const float*)d_in[6];
    const float* b_ih   = (const float*)d_in[7];
    const float* W_hh   = (const float*)d_in[8];
    const float* b_hh   = (const float*)d_in[9];
    const float* W_att  = (const float*)d_in[10];
    const float* b_att  = (const float*)d_in[11];
    const float* v      = (const float*)d_in[12];
    const float* W_ah   = (const float*)d_in[13];
    const float* b_ah   = (const float*)d_in[14];
    const float* W_out  = (const float*)d_in[15];
    const float* b_out  = (const float*)d_in[16];
    float* out = (float*)d_out;

    // flattened pytree: [output(V), h(H), c(H), x_t(H), w(S)]
    bool full = (out_size >= V_DIM + 3 * H_DIM + S_LEN);
    float* out_h  = full ? out + V_DIM              : nullptr;
    float* out_c  = full ? out + V_DIM + H_DIM      : nullptr;
    float* out_xt = full ? out + V_DIM + 2 * H_DIM  : nullptr;
    float* out_w  = full ? out + V_DIM + 3 * H_DIM  : nullptr;

    lstm_kernel   <<<128, 256>>>(word, lastc, h0, c0, emb, W_ih, b_ih, W_hh, b_hh, out_h, out_c);
    hterm_kernel  <<<128, 256>>>(W_att, b_att);
    scores_kernel <<<dim3(NT, S_LEN / BM), 256>>>(enc, W_att, v);
    softmax_kernel<<<1, 1024>>>(out_w);
    context_kernel<<<dim3(16, 4), 256>>>(enc);
    xt_kernel     <<<128, 256>>>(W_ah, b_ah, out_xt);
    logits_kernel <<<V_DIM / 8, 256>>>(W_out, b_out);
    sumexp_kernel <<<32, 256>>>();
    writeout_kernel<<<125, 256>>>(out);
}

// round 3
// speedup vs baseline: 6.7175x; 1.6779x over previous
#include <cuda_runtime.h>
#include <math.h>
#include <stdint.h>

#define S_LEN 2048
#define E_DIM 1024
#define H_DIM 1024
#define V_DIM 32000
#define EH    2048   // E+H
#define NT    16     // number of N tiles in scores GEMM (1024/64)

// ---------------- scratch (no allocations allowed) ----------------
__device__ float d_h[H_DIM];
__device__ float d_c[H_DIM];
__device__ float d_t[H_DIM];           // W_att[:, :H] @ h + b_att
__device__ float d_part[NT][S_LEN];    // partial scores per n-tile
__device__ float d_wbuf[S_LEN];
__device__ float d_ctx[E_DIM];
__device__ float d_xt[H_DIM];
__device__ float d_logits[V_DIM];
__device__ float d_red[2];             // [0]=max logit, [1]=sum exp

__device__ __forceinline__ void atomicMaxFloat(float* addr, float val) {
    if (val >= 0.0f) atomicMax((int*)addr, __float_as_int(val));
    else             atomicMin((unsigned int*)addr, __float_as_uint(val));
}

__device__ __forceinline__ float sigmoidf(float x) { return 1.0f / (1.0f + expf(-x)); }

__device__ __forceinline__ uint32_t f2tf32(float x) {
    uint32_t u;
    asm("cvt.rna.tf32.f32 %0, %1;" : "=r"(u) : "f"(x));
    return u;
}

// ---------------- K1: LSTM step -> h, c ----------------
__global__ void lstm_kernel(const int* __restrict__ word_input,
                            const float* __restrict__ last_ctx,
                            const float* __restrict__ h0,
                            const float* __restrict__ c0,
                            const float* __restrict__ emb,
                            const float* __restrict__ W_ih,
                            const float* __restrict__ b_ih,
                            const float* __restrict__ W_hh,
                            const float* __restrict__ b_hh,
                            float* out_h, float* out_c)
{
    __shared__ float sin_[EH + H_DIM];  // [lstm_in(2048) | h_prev(1024)]
    int tid = threadIdx.x;
    int word = word_input[0];
    for (int i = tid; i < H_DIM; i += blockDim.x) {
        sin_[i]          = last_ctx[i];
        sin_[H_DIM + i]  = emb[(size_t)word * E_DIM + i];
        sin_[EH + i]     = h0[i];
    }
    __syncthreads();

    int warp = blockIdx.x * (blockDim.x >> 5) + (tid >> 5);
    int lane = tid & 31;
    if (warp >= H_DIM) return;
    int j = warp;

    float acc0 = 0.f, acc1 = 0.f, acc2 = 0.f, acc3 = 0.f;
    const float* r0 = W_ih + (size_t)(j           ) * EH;
    const float* r1 = W_ih + (size_t)(j +   H_DIM ) * EH;
    const float* r2 = W_ih + (size_t)(j + 2*H_DIM ) * EH;
    const float* r3 = W_ih + (size_t)(j + 3*H_DIM ) * EH;
    for (int k = lane * 4; k < EH; k += 128) {
        float4 x = *(const float4*)&sin_[k];
        float4 w;
        w = *(const float4*)&r0[k]; acc0 += w.x*x.x + w.y*x.y + w.z*x.z + w.w*x.w;
        w = *(const float4*)&r1[k]; acc1 += w.x*x.x + w.y*x.y + w.z*x.z + w.w*x.w;
        w = *(const float4*)&r2[k]; acc2 += w.x*x.x + w.y*x.y + w.z*x.z + w.w*x.w;
        w = *(const float4*)&r3[k]; acc3 += w.x*x.x + w.y*x.y + w.z*x.z + w.w*x.w;
    }
    r0 = W_hh + (size_t)(j           ) * H_DIM;
    r1 = W_hh + (size_t)(j +   H_DIM ) * H_DIM;
    r2 = W_hh + (size_t)(j + 2*H_DIM ) * H_DIM;
    r3 = W_hh + (size_t)(j + 3*H_DIM ) * H_DIM;
    for (int k = lane * 4; k < H_DIM; k += 128) {
        float4 x = *(const float4*)&sin_[EH + k];
        float4 w;
        w = *(const float4*)&r0[k]; acc0 += w.x*x.x + w.y*x.y + w.z*x.z + w.w*x.w;
        w = *(const float4*)&r1[k]; acc1 += w.x*x.x + w.y*x.y + w.z*x.z + w.w*x.w;
        w = *(const float4*)&r2[k]; acc2 += w.x*x.x + w.y*x.y + w.z*x.z + w.w*x.w;
        w = *(const float4*)&r3[k]; acc3 += w.x*x.x + w.y*x.y + w.z*x.z + w.w*x.w;
    }
    #pragma unroll
    for (int off = 16; off; off >>= 1) {
        acc0 += __shfl_down_sync(0xffffffffu, acc0, off);
        acc1 += __shfl_down_sync(0xffffffffu, acc1, off);
        acc2 += __shfl_down_sync(0xffffffffu, acc2, off);
        acc3 += __shfl_down_sync(0xffffffffu, acc3, off);
    }
    if (lane == 0) {
        float gi = acc0 + b_ih[j]           + b_hh[j];
        float gf = acc1 + b_ih[j +   H_DIM] + b_hh[j +   H_DIM];
        float gg = acc2 + b_ih[j + 2*H_DIM] + b_hh[j + 2*H_DIM];
        float go = acc3 + b_ih[j + 3*H_DIM] + b_hh[j + 3*H_DIM];
        float iv = sigmoidf(gi);
        float fv = sigmoidf(gf);
        float gv = tanhf(gg);
        float ov = sigmoidf(go);
        float cv = fv * c0[j] + iv * gv;
        float hv = ov * tanhf(cv);
        d_h[j] = hv; d_c[j] = cv;
        if (out_h) out_h[j] = hv;
        if (out_c) out_c[j] = cv;
    }
}

// ---------------- K2: t_j = W_att[j, :H] . h + b_att[j] ----------------
__global__ void hterm_kernel(const float* __restrict__ W_att,
                             const float* __restrict__ b_att)
{
    __shared__ float sh[H_DIM];
    int tid = threadIdx.x;
    for (int i = tid; i < H_DIM; i += blockDim.x) sh[i] = d_h[i];
    __syncthreads();
    int warp = blockIdx.x * (blockDim.x >> 5) + (tid >> 5);
    int lane = tid & 31;
    if (warp >= H_DIM) return;
    const float* row = W_att + (size_t)warp * EH;
    float acc = 0.f;
    for (int k = lane * 4; k < H_DIM; k += 128) {
        float4 w = *(const float4*)&row[k];
        float4 x = *(const float4*)&sh[k];
        acc += w.x*x.x + w.y*x.y + w.z*x.z + w.w*x.w;
    }
    #pragma unroll
    for (int off = 16; off; off >>= 1) acc += __shfl_down_sync(0xffffffffu, acc, off);
    if (lane == 0) d_t[warp] = acc + b_att[warp];
}

// ---------------- K3: scores GEMM via tf32 mma.sync ----------------
// block (nt, mt): d_part[nt][s] = sum_{n in tile nt} v[n] * tanh( enc[s,:] . W_att[n, H:] + t[n] )
#define SBM 128
#define SBN 64
#define SBK 32
#define SKPAD 4

__device__ __forceinline__ void mma_tf32(float* c, const uint32_t* a, const uint32_t* b) {
    asm volatile(
        "mma.sync.aligned.m16n8k8.row.col.f32.tf32.tf32.f32 "
        "{%0,%1,%2,%3}, {%4,%5,%6,%7}, {%8,%9}, {%0,%1,%2,%3};"
        : "+f"(c[0]), "+f"(c[1]), "+f"(c[2]), "+f"(c[3])
        : "r"(a[0]), "r"(a[1]), "r"(a[2]), "r"(a[3]), "r"(b[0]), "r"(b[1]));
}

__global__ __launch_bounds__(256, 2)
void scores_kernel(const float* __restrict__ enc,
                   const float* __restrict__ W_att,
                   const float* __restrict__ v)
{
    __shared__ uint32_t As[SBM][SBK + SKPAD];   // tf32 bits
    __shared__ uint32_t Bs[SBN][SBK + SKPAD];
    __shared__ float srow[2][SBM];

    int tid  = threadIdx.x;
    int warp = tid >> 5, lane = tid & 31;
    int g = lane >> 2, tg = lane & 3;
    int m0 = blockIdx.y * SBM;
    int n0 = blockIdx.x * SBN;
    int wm = (warp >> 1) * 32;      // warp M offset within block (0,32,64,96)
    int wn = (warp & 1) * 32;       // warp N offset within block (0,32)

    float c[2][4][4];
    #pragma unroll
    for (int mt = 0; mt < 2; mt++)
        #pragma unroll
        for (int nt = 0; nt < 4; nt++)
            #pragma unroll
            for (int i = 0; i < 4; i++) c[mt][nt][i] = 0.f;

    int lrow = tid >> 3;            // 0..31
    int lcol = (tid & 7) * 4;       // 0,4,...,28

    for (int kt = 0; kt < E_DIM; kt += SBK) {
        // stage A: 128x32 (4 float4 per thread)
        #pragma unroll
        for (int i = 0; i < 4; i++) {
            int r = lrow + i * 32;
            float4 x = *(const float4*)&enc[(size_t)(m0 + r) * E_DIM + kt + lcol];
            As[r][lcol + 0] = f2tf32(x.x);
            As[r][lcol + 1] = f2tf32(x.y);
            As[r][lcol + 2] = f2tf32(x.z);
            As[r][lcol + 3] = f2tf32(x.w);
        }
        // stage B: 64x32 (2 float4 per thread)
        #pragma unroll
        for (int i = 0; i < 2; i++) {
            int r = lrow + i * 32;
            float4 x = *(const float4*)&W_att[(size_t)(n0 + r) * EH + H_DIM + kt + lcol];
            Bs[r][lcol + 0] = f2tf32(x.x);
            Bs[r][lcol + 1] = f2tf32(x.y);
            Bs[r][lcol + 2] = f2tf32(x.z);
            Bs[r][lcol + 3] = f2tf32(x.w);
        }
        __syncthreads();

        #pragma unroll
        for (int ks = 0; ks < 4; ks++) {
            int k0 = ks * 8;
            uint32_t a[2][4], b[4][2];
            #pragma unroll
            for (int mt = 0; mt < 2; mt++) {
                int r = wm + mt * 16 + g;
                a[mt][0] = As[r    ][k0 + tg    ];
                a[mt][1] = As[r + 8][k0 + tg    ];
                a[mt][2] = As[r    ][k0 + tg + 4];
                a[mt][3] = As[r + 8][k0 + tg + 4];
            }
            #pragma unroll
            for (int nt = 0; nt < 4; nt++) {
                int r = wn + nt * 8 + g;
                b[nt][0] = Bs[r][k0 + tg    ];
                b[nt][1] = Bs[r][k0 + tg + 4];
            }
            #pragma unroll
            for (int mt = 0; mt < 2; mt++)
                #pragma unroll
                for (int nt = 0; nt < 4; nt++)
                    mma_tf32(c[mt][nt], a[mt], b[nt]);
        }
        __syncthreads();
    }

    // epilogue: fold N into per-row partial scores
    #pragma unroll
    for (int mt = 0; mt < 2; mt++) {
        float p0 = 0.f, p1 = 0.f;   // rows (wm+mt*16+g), (+8)
        #pragma unroll
        for (int nt = 0; nt < 4; nt++) {
            #pragma unroll
            for (int cc = 0; cc < 2; cc++) {
                int n = n0 + wn + nt * 8 + tg * 2 + cc;
                float tn = d_t[n];
                float vn = v[n];
                p0 += vn * tanhf(c[mt][nt][cc]     + tn);
                p1 += vn * tanhf(c[mt][nt][2 + cc] + tn);
            }
        }
        // reduce over tg lanes (same g, tg=0..3)
        p0 += __shfl_xor_sync(0xffffffffu, p0, 1);
        p0 += __shfl_xor_sync(0xffffffffu, p0, 2);
        p1 += __shfl_xor_sync(0xffffffffu, p1, 1);
        p1 += __shfl_xor_sync(0xffffffffu, p1, 2);
        if (tg == 0) {
            srow[warp & 1][wm + mt * 16 + g    ] = p0;
            srow[warp & 1][wm + mt * 16 + g + 8] = p1;
        }
    }
    __syncthreads();
    if (tid < SBM)
        d_part[blockIdx.x][m0 + tid] = srow[0][tid] + srow[1][tid];
}

// ---------------- K4: fold partials + softmax (single block, 1024 thr) ----------------
__global__ void softmax_kernel(float* out_w)
{
    __shared__ float red[32];
    __shared__ float sc[S_LEN];
    __shared__ float smax, ssum;
    int tid = threadIdx.x;
    int lane = tid & 31, warp = tid >> 5;

    float m = -1e30f;
    for (int i = tid; i < S_LEN; i += 1024) {
        float s = 0.f;
        #pragma unroll
        for (int p = 0; p < NT; p++) s += d_part[p][i];
        sc[i] = s;
        m = fmaxf(m, s);
    }
    #pragma unroll
    for (int off = 16; off; off >>= 1) m = fmaxf(m, __shfl_xor_sync(0xffffffffu, m, off));
    if (lane == 0) red[warp] = m;
    __syncthreads();
    if (warp == 0) {
        m = red[lane];
        #pragma unroll
        for (int off = 16; off; off >>= 1) m = fmaxf(m, __shfl_xor_sync(0xffffffffu, m, off));
        if (lane == 0) smax = m;
    }
    __syncthreads();
    float mx = smax;
    float sum = 0.f;
    for (int i = tid; i < S_LEN; i += 1024) sum += expf(sc[i] - mx);
    #pragma unroll
    for (int off = 16; off; off >>= 1) sum += __shfl_xor_sync(0xffffffffu, sum, off);
    if (lane == 0) red[warp] = sum;
    __syncthreads();
    if (warp == 0) {
        sum = red[lane];
        #pragma unroll
        for (int off = 16; off; off >>= 1) sum += __shfl_xor_sync(0xffffffffu, sum, off);
        if (lane == 0) ssum = sum;
    }
    __syncthreads();
    float inv = 1.0f / ssum;
    for (int i = tid; i < S_LEN; i += 1024) {
        float w = expf(sc[i] - mx) * inv;
        d_wbuf[i] = w;
        if (out_w) out_w[i] = w;
    }
    for (int i = tid; i < E_DIM; i += 1024) d_ctx[i] = 0.f;  // zero for K5 atomics
}

// ---------------- K5: context = w @ enc ----------------
__global__ void context_kernel(const float* __restrict__ enc)
{
    int e  = blockIdx.y * 256 + threadIdx.x;
    int s0 = blockIdx.x * 128;
    float acc = 0.f;
    for (int s = s0; s < s0 + 128; s++)
        acc += d_wbuf[s] * enc[(size_t)s * E_DIM + e];
    atomicAdd(&d_ctx[e], acc);
}

// ---------------- K6: x_t = tanh(W_ah @ [context; h] + b_ah) ----------------
__global__ void xt_kernel(const float* __restrict__ W_ah,
                          const float* __restrict__ b_ah,
                          float* out_xt)
{
    __shared__ float cat[EH];
    int tid = threadIdx.x;
    for (int i = tid; i < H_DIM; i += blockDim.x) {
        cat[i]          = d_ctx[i];
        cat[H_DIM + i]  = d_h[i];
    }
    __syncthreads();
    if (blockIdx.x == 0 && tid == 0) { d_red[0] = -1e30f; d_red[1] = 0.f; }
    int warp = blockIdx.x * (blockDim.x >> 5) + (tid >> 5);
    int lane = tid & 31;
    if (warp >= H_DIM) return;
    const float* row = W_ah + (size_t)warp * EH;
    float acc = 0.f;
    for (int k = lane * 4; k < EH; k += 128) {
        float4 w = *(const float4*)&row[k];
        float4 x = *(const float4*)&cat[k];
        acc += w.x*x.x + w.y*x.y + w.z*x.z + w.w*x.w;
    }
    #pragma unroll
    for (int off = 16; off; off >>= 1) acc += __shfl_down_sync(0xffffffffu, acc, off);
    if (lane == 0) {
        float x = tanhf(acc + b_ah[warp]);
        d_xt[warp] = x;
        if (out_xt) out_xt[warp] = x;
    }
}

// ---------------- K7: logits = W_out @ x_t + b_out (+ global max) ----------------
__global__ void logits_kernel(const float* __restrict__ W_out,
                              const float* __restrict__ b_out)
{
    __shared__ float sx[H_DIM];
    __shared__ float wmax[8];
    int tid = threadIdx.x;
    for (int i = tid; i < H_DIM; i += 256) sx[i] = d_xt[i];
    __syncthreads();
    int warpl = tid >> 5, lane = tid & 31;
    int row = blockIdx.x * 8 + warpl;
    const float* wr = W_out + (size_t)row * H_DIM;
    float acc = 0.f;
    for (int k = lane * 4; k < H_DIM; k += 128) {
        float4 w = *(const float4*)&wr[k];
        float4 x = *(const float4*)&sx[k];
        acc += w.x*x.x + w.y*x.y + w.z*x.z + w.w*x.w;
    }
    #pragma unroll
    for (int off = 16; off; off >>= 1) acc += __shfl_down_sync(0xffffffffu, acc, off);
    if (lane == 0) {
        float lg = acc + b_out[row];
        d_logits[row] = lg;
        wmax[warpl] = lg;
    }
    __syncthreads();
    if (tid == 0) {
        float m = wmax[0];
        #pragma unroll
        for (int i = 1; i < 8; i++) m = fmaxf(m, wmax[i]);
        atomicMaxFloat(&d_red[0], m);
    }
}

// ---------------- K8: sum of exp(logit - max) ----------------
__global__ void sumexp_kernel()
{
    __shared__ float red[256];
    int tid = threadIdx.x;
    float mx = d_red[0];
    float acc = 0.f;
    for (int r = blockIdx.x * 256 + tid; r < V_DIM; r += gridDim.x * 256)
        acc += expf(d_logits[r] - mx);
    red[tid] = acc; __syncthreads();
    for (int off = 128; off; off >>= 1) {
        if (tid < off) red[tid] += red[tid + off];
        __syncthreads();
    }
    if (tid == 0) atomicAdd(&d_red[1], red[0]);
}

// ---------------- K9: out = logits - logsumexp ----------------
__global__ void writeout_kernel(float* __restrict__ out)
{
    float lse = d_red[0] + logf(d_red[1]);
    int r = blockIdx.x * 256 + threadIdx.x;
    if (r < V_DIM) out[r] = d_logits[r] - lse;
}

// ---------------- launch ----------------
extern "C" void kernel_launch(void* const* d_in, const int* in_sizes, int n_in,
                              void* d_out, int out_size)
{
    const float* enc    = (const float*)d_in[0];
    const int*   word   = (const int*)  d_in[1];
    const float* lastc  = (const float*)d_in[2];
    const float* h0     = (const float*)d_in[3];
    const float* c0     = (const float*)d_in[4];
    const float* emb    = (const float*)d_in[5];
    const float* W_ih   = (const float*)d_in[6];
    const float* b_ih   = (const float*)d_in[7];
    const float* W_hh   = (const float*)d_in[8];
    const float* b_hh   = (const float*)d_in[9];
    const float* W_att  = (const float*)d_in[10];
    const float* b_att  = (const float*)d_in[11];
    const float* v      = (const float*)d_in[12];
    const float* W_ah   = (const float*)d_in[13];
    const float* b_ah   = (const float*)d_in[14];
    const float* W_out  = (const float*)d_in[15];
    const float* b_out  = (const float*)d_in[16];
    float* out = (float*)d_out;

    // flattened pytree: [output(V), h(H), c(H), x_t(H), w(S)]
    bool full = (out_size >= V_DIM + 3 * H_DIM + S_LEN);
    float* out_h  = full ? out + V_DIM              : nullptr;
    float* out_c  = full ? out + V_DIM + H_DIM      : nullptr;
    float* out_xt = full ? out + V_DIM + 2 * H_DIM  : nullptr;
    float* out_w  = full ? out + V_DIM + 3 * H_DIM  : nullptr;

    lstm_kernel   <<<128, 256>>>(word, lastc, h0, c0, emb, W_ih, b_ih, W_hh, b_hh, out_h, out_c);
    hterm_kernel  <<<128, 256>>>(W_att, b_att);
    scores_kernel <<<dim3(NT, S_LEN / SBM), 256>>>(enc, W_att, v);
    softmax_kernel<<<1, 1024>>>(out_w);
    context_kernel<<<dim3(16, 4), 256>>>(enc);
    xt_kernel     <<<128, 256>>>(W_ah, b_ah, out_xt);
    logits_kernel <<<V_DIM / 8, 256>>>(W_out, b_out);
    sumexp_kernel <<<32, 256>>>();
    writeout_kernel<<<125, 256>>>(out);
}

// round 4
// speedup vs baseline: 9.4687x; 1.4095x over previous
#include <cuda_runtime.h>
#include <math.h>
#include <stdint.h>

#define S_LEN 2048
#define E_DIM 1024
#define H_DIM 1024
#define V_DIM 32000
#define EH    2048   // E+H
#define NT    16     // number of N tiles in scores GEMM (1024/64)

// ---------------- scratch (no allocations allowed) ----------------
__device__ float d_gates[4 * H_DIM];
__device__ float d_h[H_DIM];
__device__ float d_t[H_DIM];           // W_att[:, :H] @ h + b_att
__device__ float d_part[NT][S_LEN];    // partial scores per n-tile
__device__ float d_wbuf[S_LEN];
__device__ float d_ctx[E_DIM];
__device__ float d_xt[H_DIM];
__device__ float d_logits[V_DIM];
__device__ float d_sumexp;

__device__ __forceinline__ float sigmoidf(float x) { return 1.0f / (1.0f + expf(-x)); }

__device__ __forceinline__ uint32_t f2tf32(float x) {
    uint32_t u;
    asm("cvt.rna.tf32.f32 %0, %1;" : "=r"(u) : "f"(x));
    return u;
}

// ---------------- K1: gate rows -> d_gates[4096] ----------------
// 512 blocks x 8 warps; warp r computes W_ih[r].lstm_in + W_hh[r].h0 + biases
__global__ void gates_kernel(const int* __restrict__ word_input,
                             const float* __restrict__ last_ctx,
                             const float* __restrict__ h0,
                             const float* __restrict__ emb,
                             const float* __restrict__ W_ih,
                             const float* __restrict__ b_ih,
                             const float* __restrict__ W_hh,
                             const float* __restrict__ b_hh)
{
    __shared__ float sin_[EH + H_DIM];  // [lstm_in(2048) | h_prev(1024)]
    int tid = threadIdx.x;
    int word = word_input[0];
    for (int i = tid; i < H_DIM; i += blockDim.x) {
        sin_[i]          = last_ctx[i];
        sin_[H_DIM + i]  = emb[(size_t)word * E_DIM + i];
        sin_[EH + i]     = h0[i];
    }
    __syncthreads();

    int r = blockIdx.x * 8 + (tid >> 5);   // gate row 0..4095
    int lane = tid & 31;

    const float* wrow = W_ih + (size_t)r * EH;
    float acc = 0.f;
    #pragma unroll
    for (int k = lane * 4; k < EH; k += 128) {
        float4 w = *(const float4*)&wrow[k];
        float4 x = *(const float4*)&sin_[k];
        acc += w.x*x.x + w.y*x.y + w.z*x.z + w.w*x.w;
    }
    const float* hrow = W_hh + (size_t)r * H_DIM;
    #pragma unroll
    for (int k = lane * 4; k < H_DIM; k += 128) {
        float4 w = *(const float4*)&hrow[k];
        float4 x = *(const float4*)&sin_[EH + k];
        acc += w.x*x.x + w.y*x.y + w.z*x.z + w.w*x.w;
    }
    #pragma unroll
    for (int off = 16; off; off >>= 1) acc += __shfl_down_sync(0xffffffffu, acc, off);
    if (lane == 0) d_gates[r] = acc + b_ih[r] + b_hh[r];
}

// ---------------- K2: h from gates (redundant per block) + t = W_att[:, :H].h + b_att ----------------
__global__ void hterm_kernel(const float* __restrict__ W_att,
                             const float* __restrict__ b_att,
                             const float* __restrict__ c0,
                             float* out_h, float* out_c)
{
    __shared__ float sh[H_DIM];
    int tid = threadIdx.x;
    for (int j = tid; j < H_DIM; j += blockDim.x) {
        float iv = sigmoidf(d_gates[j]);
        float fv = sigmoidf(d_gates[j +   H_DIM]);
        float gv = tanhf  (d_gates[j + 2*H_DIM]);
        float ov = sigmoidf(d_gates[j + 3*H_DIM]);
        float cv = fv * c0[j] + iv * gv;
        float hv = ov * tanhf(cv);
        sh[j] = hv;
        if (blockIdx.x == 0) {
            d_h[j] = hv;
            if (out_h) out_h[j] = hv;
            if (out_c) out_c[j] = cv;
        }
    }
    __syncthreads();

    int warp = blockIdx.x * (blockDim.x >> 5) + (tid >> 5);
    int lane = tid & 31;
    if (warp >= H_DIM) return;
    const float* row = W_att + (size_t)warp * EH;
    float acc = 0.f;
    #pragma unroll
    for (int k = lane * 4; k < H_DIM; k += 128) {
        float4 w = *(const float4*)&row[k];
        float4 x = *(const float4*)&sh[k];
        acc += w.x*x.x + w.y*x.y + w.z*x.z + w.w*x.w;
    }
    #pragma unroll
    for (int off = 16; off; off >>= 1) acc += __shfl_down_sync(0xffffffffu, acc, off);
    if (lane == 0) d_t[warp] = acc + b_att[warp];
}

// ---------------- K3: scores GEMM via tf32 mma.sync, prefetch-pipelined ----------------
#define SBM 128
#define SBN 64
#define SBK 32
#define SKPAD 4
#define NKI (E_DIM / SBK)

__device__ __forceinline__ void mma_tf32(float* c, const uint32_t* a, const uint32_t* b) {
    asm volatile(
        "mma.sync.aligned.m16n8k8.row.col.f32.tf32.tf32.f32 "
        "{%0,%1,%2,%3}, {%4,%5,%6,%7}, {%8,%9}, {%0,%1,%2,%3};"
        : "+f"(c[0]), "+f"(c[1]), "+f"(c[2]), "+f"(c[3])
        : "r"(a[0]), "r"(a[1]), "r"(a[2]), "r"(a[3]), "r"(b[0]), "r"(b[1]));
}

__global__ __launch_bounds__(256, 2)
void scores_kernel(const float* __restrict__ enc,
                   const float* __restrict__ W_att,
                   const float* __restrict__ v)
{
    __shared__ uint32_t As[SBM][SBK + SKPAD];   // tf32 bits
    __shared__ uint32_t Bs[SBN][SBK + SKPAD];
    __shared__ float srow[2][SBM];

    int tid  = threadIdx.x;
    int warp = tid >> 5, lane = tid & 31;
    int g = lane >> 2, tg = lane & 3;
    int m0 = blockIdx.y * SBM;
    int n0 = blockIdx.x * SBN;
    int wm = (warp >> 1) * 32;      // warp M offset (0,32,64,96)
    int wn = (warp & 1) * 32;       // warp N offset (0,32)

    float c[2][4][4];
    #pragma unroll
    for (int mt = 0; mt < 2; mt++)
        #pragma unroll
        for (int nt = 0; nt < 4; nt++)
            #pragma unroll
            for (int i = 0; i < 4; i++) c[mt][nt][i] = 0.f;

    int lrow = tid >> 3;            // 0..31
    int lcol = (tid & 7) * 4;       // 0,4,...,28

    const float* aptr = enc   + (size_t)(m0 + lrow) * E_DIM + lcol;
    const float* bptr = W_att + (size_t)(n0 + lrow) * EH + H_DIM + lcol;

    float4 ra[4], rb[2];
    // prologue: fetch tile 0
    #pragma unroll
    for (int i = 0; i < 4; i++) ra[i] = *(const float4*)(aptr + (size_t)i * 32 * E_DIM);
    #pragma unroll
    for (int i = 0; i < 2; i++) rb[i] = *(const float4*)(bptr + (size_t)i * 32 * EH);

    for (int kt_i = 0; kt_i < NKI; kt_i++) {
        // store staged regs (tf32) into smem
        #pragma unroll
        for (int i = 0; i < 4; i++) {
            int r = lrow + i * 32;
            As[r][lcol + 0] = f2tf32(ra[i].x);
            As[r][lcol + 1] = f2tf32(ra[i].y);
            As[r][lcol + 2] = f2tf32(ra[i].z);
            As[r][lcol + 3] = f2tf32(ra[i].w);
        }
        #pragma unroll
        for (int i = 0; i < 2; i++) {
            int r = lrow + i * 32;
            Bs[r][lcol + 0] = f2tf32(rb[i].x);
            Bs[r][lcol + 1] = f2tf32(rb[i].y);
            Bs[r][lcol + 2] = f2tf32(rb[i].z);
            Bs[r][lcol + 3] = f2tf32(rb[i].w);
        }
        __syncthreads();

        // prefetch next tile while mma consumes smem
        if (kt_i + 1 < NKI) {
            const float* an = aptr + (size_t)(kt_i + 1) * SBK;
            const float* bn = bptr + (size_t)(kt_i + 1) * SBK;
            #pragma unroll
            for (int i = 0; i < 4; i++) ra[i] = *(const float4*)(an + (size_t)i * 32 * E_DIM);
            #pragma unroll
            for (int i = 0; i < 2; i++) rb[i] = *(const float4*)(bn + (size_t)i * 32 * EH);
        }

        #pragma unroll
        for (int ks = 0; ks < 4; ks++) {
            int k0 = ks * 8;
            uint32_t a[2][4], b[4][2];
            #pragma unroll
            for (int mt = 0; mt < 2; mt++) {
                int r = wm + mt * 16 + g;
                a[mt][0] = As[r    ][k0 + tg    ];
                a[mt][1] = As[r + 8][k0 + tg    ];
                a[mt][2] = As[r    ][k0 + tg + 4];
                a[mt][3] = As[r + 8][k0 + tg + 4];
            }
            #pragma unroll
            for (int nt = 0; nt < 4; nt++) {
                int r = wn + nt * 8 + g;
                b[nt][0] = Bs[r][k0 + tg    ];
                b[nt][1] = Bs[r][k0 + tg + 4];
            }
            #pragma unroll
            for (int mt = 0; mt < 2; mt++)
                #pragma unroll
                for (int nt = 0; nt < 4; nt++)
                    mma_tf32(c[mt][nt], a[mt], b[nt]);
        }
        __syncthreads();
    }

    // epilogue: fold N into per-row partial scores
    #pragma unroll
    for (int mt = 0; mt < 2; mt++) {
        float p0 = 0.f, p1 = 0.f;   // rows (wm+mt*16+g), (+8)
        #pragma unroll
        for (int nt = 0; nt < 4; nt++) {
            #pragma unroll
            for (int cc = 0; cc < 2; cc++) {
                int n = n0 + wn + nt * 8 + tg * 2 + cc;
                float tn = d_t[n];
                float vn = v[n];
                p0 += vn * tanhf(c[mt][nt][cc]     + tn);
                p1 += vn * tanhf(c[mt][nt][2 + cc] + tn);
            }
        }
        p0 += __shfl_xor_sync(0xffffffffu, p0, 1);
        p0 += __shfl_xor_sync(0xffffffffu, p0, 2);
        p1 += __shfl_xor_sync(0xffffffffu, p1, 1);
        p1 += __shfl_xor_sync(0xffffffffu, p1, 2);
        if (tg == 0) {
            srow[warp & 1][wm + mt * 16 + g    ] = p0;
            srow[warp & 1][wm + mt * 16 + g + 8] = p1;
        }
    }
    __syncthreads();
    if (tid < SBM)
        d_part[blockIdx.x][m0 + tid] = srow[0][tid] + srow[1][tid];
}

// ---------------- K4: fold partials + softmax (single block, 1024 thr) ----------------
__global__ void softmax_kernel(float* out_w)
{
    __shared__ float red[32];
    __shared__ float sc[S_LEN];
    __shared__ float smax, ssum;
    int tid = threadIdx.x;
    int lane = tid & 31, warp = tid >> 5;

    float m = -1e30f;
    for (int i = tid; i < S_LEN; i += 1024) {
        float s = 0.f;
        #pragma unroll
        for (int p = 0; p < NT; p++) s += d_part[p][i];
        sc[i] = s;
        m = fmaxf(m, s);
    }
    #pragma unroll
    for (int off = 16; off; off >>= 1) m = fmaxf(m, __shfl_xor_sync(0xffffffffu, m, off));
    if (lane == 0) red[warp] = m;
    __syncthreads();
    if (warp == 0) {
        m = red[lane];
        #pragma unroll
        for (int off = 16; off; off >>= 1) m = fmaxf(m, __shfl_xor_sync(0xffffffffu, m, off));
        if (lane == 0) smax = m;
    }
    __syncthreads();
    float mx = smax;
    float sum = 0.f;
    for (int i = tid; i < S_LEN; i += 1024) sum += expf(sc[i] - mx);
    #pragma unroll
    for (int off = 16; off; off >>= 1) sum += __shfl_xor_sync(0xffffffffu, sum, off);
    if (lane == 0) red[warp] = sum;
    __syncthreads();
    if (warp == 0) {
        sum = red[lane];
        #pragma unroll
        for (int off = 16; off; off >>= 1) sum += __shfl_xor_sync(0xffffffffu, sum, off);
        if (lane == 0) ssum = sum;
    }
    __syncthreads();
    float inv = 1.0f / ssum;
    for (int i = tid; i < S_LEN; i += 1024) {
        float w = expf(sc[i] - mx) * inv;
        d_wbuf[i] = w;
        if (out_w) out_w[i] = w;
    }
    for (int i = tid; i < E_DIM; i += 1024) d_ctx[i] = 0.f;  // zero for K5 atomics
}

// ---------------- K5: context = w @ enc ----------------
__global__ void context_kernel(const float* __restrict__ enc)
{
    int e  = blockIdx.y * 256 + threadIdx.x;
    int s0 = blockIdx.x * 128;
    float a0 = 0.f, a1 = 0.f, a2 = 0.f, a3 = 0.f;
    #pragma unroll 4
    for (int s = s0; s < s0 + 128; s += 4) {
        a0 += d_wbuf[s    ] * enc[(size_t)(s    ) * E_DIM + e];
        a1 += d_wbuf[s + 1] * enc[(size_t)(s + 1) * E_DIM + e];
        a2 += d_wbuf[s + 2] * enc[(size_t)(s + 2) * E_DIM + e];
        a3 += d_wbuf[s + 3] * enc[(size_t)(s + 3) * E_DIM + e];
    }
    atomicAdd(&d_ctx[e], (a0 + a1) + (a2 + a3));
}

// ---------------- K6: x_t = tanh(W_ah @ [context; h] + b_ah) ----------------
__global__ void xt_kernel(const float* __restrict__ W_ah,
                          const float* __restrict__ b_ah,
                          float* out_xt)
{
    __shared__ float cat[EH];
    int tid = threadIdx.x;
    for (int i = tid; i < H_DIM; i += blockDim.x) {
        cat[i]          = d_ctx[i];
        cat[H_DIM + i]  = d_h[i];
    }
    __syncthreads();
    if (blockIdx.x == 0 && tid == 0) d_sumexp = 0.f;
    int warp = blockIdx.x * (blockDim.x >> 5) + (tid >> 5);
    int lane = tid & 31;
    if (warp >= H_DIM) return;
    const float* row = W_ah + (size_t)warp * EH;
    float acc = 0.f;
    #pragma unroll
    for (int k = lane * 4; k < EH; k += 128) {
        float4 w = *(const float4*)&row[k];
        float4 x = *(const float4*)&cat[k];
        acc += w.x*x.x + w.y*x.y + w.z*x.z + w.w*x.w;
    }
    #pragma unroll
    for (int off = 16; off; off >>= 1) acc += __shfl_down_sync(0xffffffffu, acc, off);
    if (lane == 0) {
        float x = tanhf(acc + b_ah[warp]);
        d_xt[warp] = x;
        if (out_xt) out_xt[warp] = x;
    }
}

// ---------------- K7: logits = W_out @ x_t + b_out ----------------
__global__ void logits_kernel(const float* __restrict__ W_out,
                              const float* __restrict__ b_out)
{
    __shared__ float sx[H_DIM];
    int tid = threadIdx.x;
    for (int i = tid; i < H_DIM; i += 256) sx[i] = d_xt[i];
    __syncthreads();
    int warpl = tid >> 5, lane = tid & 31;
    int row = blockIdx.x * 8 + warpl;
    const float* wr = W_out + (size_t)row * H_DIM;
    float acc = 0.f;
    #pragma unroll
    for (int k = lane * 4; k < H_DIM; k += 128) {
        float4 w = *(const float4*)&wr[k];
        float4 x = *(const float4*)&sx[k];
        acc += w.x*x.x + w.y*x.y + w.z*x.z + w.w*x.w;
    }
    #pragma unroll
    for (int off = 16; off; off >>= 1) acc += __shfl_down_sync(0xffffffffu, acc, off);
    if (lane == 0) d_logits[row] = acc + b_out[row];
}

// ---------------- K8: sum of exp(logit) (logits are O(1): no max needed) ----------------
__global__ void sumexp_kernel()
{
    __shared__ float red[256];
    int tid = threadIdx.x;
    float acc = 0.f;
    for (int r = blockIdx.x * 256 + tid; r < V_DIM; r += gridDim.x * 256)
        acc += expf(d_logits[r]);
    red[tid] = acc; __syncthreads();
    for (int off = 128; off; off >>= 1) {
        if (tid < off) red[tid] += red[tid + off];
        __syncthreads();
    }
    if (tid == 0) atomicAdd(&d_sumexp, red[0]);
}

// ---------------- K9: out = logits - log(sumexp) ----------------
__global__ void writeout_kernel(float* __restrict__ out)
{
    float lse = logf(d_sumexp);
    int r = blockIdx.x * 256 + threadIdx.x;
    if (r < V_DIM) out[r] = d_logits[r] - lse;
}

// ---------------- launch ----------------
extern "C" void kernel_launch(void* const* d_in, const int* in_sizes, int n_in,
                              void* d_out, int out_size)
{
    const float* enc    = (const float*)d_in[0];
    const int*   word   = (const int*)  d_in[1];
    const float* lastc  = (const float*)d_in[2];
    const float* h0     = (const float*)d_in[3];
    const float* c0     = (const float*)d_in[4];
    const float* emb    = (const float*)d_in[5];
    const float* W_ih   = (const float*)d_in[6];
    const float* b_ih   = (const float*)d_in[7];
    const float* W_hh   = (const float*)d_in[8];
    const float* b_hh   = (const float*)d_in[9];
    const float* W_att  = (const float*)d_in[10];
    const float* b_att  = (const float*)d_in[11];
    const float* v      = (const float*)d_in[12];
    const float* W_ah   = (const float*)d_in[13];
    const float* b_ah   = (const float*)d_in[14];
    const float* W_out  = (const float*)d_in[15];
    const float* b_out  = (const float*)d_in[16];
    float* out = (float*)d_out;

    // flattened pytree: [output(V), h(H), c(H), x_t(H), w(S)]
    bool full = (out_size >= V_DIM + 3 * H_DIM + S_LEN);
    float* out_h  = full ? out + V_DIM              : nullptr;
    float* out_c  = full ? out + V_DIM + H_DIM      : nullptr;
    float* out_xt = full ? out + V_DIM + 2 * H_DIM  : nullptr;
    float* out_w  = full ? out + V_DIM + 3 * H_DIM  : nullptr;

    gates_kernel  <<<512, 256>>>(word, lastc, h0, emb, W_ih, b_ih, W_hh, b_hh);
    hterm_kernel  <<<128, 256>>>(W_att, b_att, c0, out_h, out_c);
    scores_kernel <<<dim3(NT, S_LEN / SBM), 256>>>(enc, W_att, v);
    softmax_kernel<<<1, 1024>>>(out_w);
    context_kernel<<<dim3(16, 4), 256>>>(enc);
    xt_kernel     <<<128, 256>>>(W_ah, b_ah, out_xt);
    logits_kernel <<<V_DIM / 8, 256>>>(W_out, b_out);
    sumexp_kernel <<<32, 256>>>();
    writeout_kernel<<<125, 256>>>(out);
}

// round 5
// speedup vs baseline: 9.9005x; 1.0456x over previous
#include <cuda_runtime.h>
#include <math.h>
#include <stdint.h>

#define S_LEN 2048
#define E_DIM 1024
#define H_DIM 1024
#define V_DIM 32000
#define EH    2048   // E+H

// ---------------- scratch (no allocations allowed) ----------------
__device__ float d_gates[4 * H_DIM];
__device__ float d_h[H_DIM];
__device__ float d_t[H_DIM];           // W_att[:, :H] @ h + b_att
__device__ float d_scores[S_LEN];
__device__ float d_ctx[E_DIM];
__device__ float d_xt[H_DIM];
__device__ float d_logits[V_DIM];
__device__ float d_sumexp;

__device__ __forceinline__ float sigmoidf(float x) { return 1.0f / (1.0f + expf(-x)); }

__device__ __forceinline__ uint32_t f2tf32(float x) {
    uint32_t u;
    asm("cvt.rna.tf32.f32 %0, %1;" : "=r"(u) : "f"(x));
    return u;
}

// ---------------- K1: gate rows -> d_gates[4096] ----------------
// 512 blocks x 8 warps; warp r computes W_ih[r].lstm_in + W_hh[r].h0 + biases
__global__ void gates_kernel(const int* __restrict__ word_input,
                             const float* __restrict__ last_ctx,
                             const float* __restrict__ h0,
                             const float* __restrict__ emb,
                             const float* __restrict__ W_ih,
                             const float* __restrict__ b_ih,
                             const float* __restrict__ W_hh,
                             const float* __restrict__ b_hh)
{
    __shared__ float sin_[EH + H_DIM];  // [lstm_in(2048) | h_prev(1024)]
    int tid = threadIdx.x;
    int word = word_input[0];
    for (int i = tid; i < H_DIM; i += blockDim.x) {
        sin_[i]          = last_ctx[i];
        sin_[H_DIM + i]  = emb[(size_t)word * E_DIM + i];
        sin_[EH + i]     = h0[i];
    }
    __syncthreads();

    int r = blockIdx.x * 8 + (tid >> 5);   // gate row 0..4095
    int lane = tid & 31;

    const float* wrow = W_ih + (size_t)r * EH;
    float acc = 0.f;
    #pragma unroll
    for (int k = lane * 4; k < EH; k += 128) {
        float4 w = *(const float4*)&wrow[k];
        float4 x = *(const float4*)&sin_[k];
        acc += w.x*x.x + w.y*x.y + w.z*x.z + w.w*x.w;
    }
    const float* hrow = W_hh + (size_t)r * H_DIM;
    #pragma unroll
    for (int k = lane * 4; k < H_DIM; k += 128) {
        float4 w = *(const float4*)&hrow[k];
        float4 x = *(const float4*)&sin_[EH + k];
        acc += w.x*x.x + w.y*x.y + w.z*x.z + w.w*x.w;
    }
    #pragma unroll
    for (int off = 16; off; off >>= 1) acc += __shfl_down_sync(0xffffffffu, acc, off);
    if (lane == 0) d_gates[r] = acc + b_ih[r] + b_hh[r];
}

// ---------------- K2: h from gates + t = W_att[:, :H].h + b_att (+ zero scratch) ----------------
__global__ void hterm_kernel(const float* __restrict__ W_att,
                             const float* __restrict__ b_att,
                             const float* __restrict__ c0,
                             float* out_h, float* out_c)
{
    __shared__ float sh[H_DIM];
    int tid = threadIdx.x;
    for (int j = tid; j < H_DIM; j += blockDim.x) {
        float iv = sigmoidf(d_gates[j]);
        float fv = sigmoidf(d_gates[j +   H_DIM]);
        float gv = tanhf  (d_gates[j + 2*H_DIM]);
        float ov = sigmoidf(d_gates[j + 3*H_DIM]);
        float cv = fv * c0[j] + iv * gv;
        float hv = ov * tanhf(cv);
        sh[j] = hv;
        if (blockIdx.x == 0) {
            d_h[j] = hv;
            d_ctx[j] = 0.f;
            if (out_h) out_h[j] = hv;
            if (out_c) out_c[j] = cv;
        }
    }
    if (blockIdx.x == 1) {
        for (int i = tid; i < S_LEN; i += blockDim.x) d_scores[i] = 0.f;
        if (tid == 0) d_sumexp = 0.f;
    }
    __syncthreads();

    int warp = blockIdx.x * (blockDim.x >> 5) + (tid >> 5);
    int lane = tid & 31;
    if (warp >= H_DIM) return;
    const float* row = W_att + (size_t)warp * EH;
    float acc = 0.f;
    #pragma unroll
    for (int k = lane * 4; k < H_DIM; k += 128) {
        float4 w = *(const float4*)&row[k];
        float4 x = *(const float4*)&sh[k];
        acc += w.x*x.x + w.y*x.y + w.z*x.z + w.w*x.w;
    }
    #pragma unroll
    for (int off = 16; off; off >>= 1) acc += __shfl_down_sync(0xffffffffu, acc, off);
    if (lane == 0) d_t[warp] = acc + b_att[warp];
}

// ---------------- K3: scores GEMM via tf32 mma.sync, prefetch-pipelined ----------------
#define SBM 128
#define SBN 64
#define SBK 32
#define SKPAD 4
#define NKI (E_DIM / SBK)

__device__ __forceinline__ void mma_tf32(float* c, const uint32_t* a, const uint32_t* b) {
    asm volatile(
        "mma.sync.aligned.m16n8k8.row.col.f32.tf32.tf32.f32 "
        "{%0,%1,%2,%3}, {%4,%5,%6,%7}, {%8,%9}, {%0,%1,%2,%3};"
        : "+f"(c[0]), "+f"(c[1]), "+f"(c[2]), "+f"(c[3])
        : "r"(a[0]), "r"(a[1]), "r"(a[2]), "r"(a[3]), "r"(b[0]), "r"(b[1]));
}

__global__ __launch_bounds__(256, 2)
void scores_kernel(const float* __restrict__ enc,
                   const float* __restrict__ W_att,
                   const float* __restrict__ v)
{
    __shared__ uint32_t As[SBM][SBK + SKPAD];   // tf32 bits
    __shared__ uint32_t Bs[SBN][SBK + SKPAD];
    __shared__ float srow[2][SBM];

    int tid  = threadIdx.x;
    int warp = tid >> 5, lane = tid & 31;
    int g = lane >> 2, tg = lane & 3;
    int m0 = blockIdx.y * SBM;
    int n0 = blockIdx.x * SBN;
    int wm = (warp >> 1) * 32;      // warp M offset (0,32,64,96)
    int wn = (warp & 1) * 32;       // warp N offset (0,32)

    float c[2][4][4];
    #pragma unroll
    for (int mt = 0; mt < 2; mt++)
        #pragma unroll
        for (int nt = 0; nt < 4; nt++)
            #pragma unroll
            for (int i = 0; i < 4; i++) c[mt][nt][i] = 0.f;

    int lrow = tid >> 3;            // 0..31
    int lcol = (tid & 7) * 4;       // 0,4,...,28

    const float* aptr = enc   + (size_t)(m0 + lrow) * E_DIM + lcol;
    const float* bptr = W_att + (size_t)(n0 + lrow) * EH + H_DIM + lcol;

    float4 ra[4], rb[2];
    #pragma unroll
    for (int i = 0; i < 4; i++) ra[i] = *(const float4*)(aptr + (size_t)i * 32 * E_DIM);
    #pragma unroll
    for (int i = 0; i < 2; i++) rb[i] = *(const float4*)(bptr + (size_t)i * 32 * EH);

    for (int kt_i = 0; kt_i < NKI; kt_i++) {
        #pragma unroll
        for (int i = 0; i < 4; i++) {
            int r = lrow + i * 32;
            As[r][lcol + 0] = f2tf32(ra[i].x);
            As[r][lcol + 1] = f2tf32(ra[i].y);
            As[r][lcol + 2] = f2tf32(ra[i].z);
            As[r][lcol + 3] = f2tf32(ra[i].w);
        }
        #pragma unroll
        for (int i = 0; i < 2; i++) {
            int r = lrow + i * 32;
            Bs[r][lcol + 0] = f2tf32(rb[i].x);
            Bs[r][lcol + 1] = f2tf32(rb[i].y);
            Bs[r][lcol + 2] = f2tf32(rb[i].z);
            Bs[r][lcol + 3] = f2tf32(rb[i].w);
        }
        __syncthreads();

        if (kt_i + 1 < NKI) {
            const float* an = aptr + (size_t)(kt_i + 1) * SBK;
            const float* bn = bptr + (size_t)(kt_i + 1) * SBK;
            #pragma unroll
            for (int i = 0; i < 4; i++) ra[i] = *(const float4*)(an + (size_t)i * 32 * E_DIM);
            #pragma unroll
            for (int i = 0; i < 2; i++) rb[i] = *(const float4*)(bn + (size_t)i * 32 * EH);
        }

        #pragma unroll
        for (int ks = 0; ks < 4; ks++) {
            int k0 = ks * 8;
            uint32_t a[2][4], b[4][2];
            #pragma unroll
            for (int mt = 0; mt < 2; mt++) {
                int r = wm + mt * 16 + g;
                a[mt][0] = As[r    ][k0 + tg    ];
                a[mt][1] = As[r + 8][k0 + tg    ];
                a[mt][2] = As[r    ][k0 + tg + 4];
                a[mt][3] = As[r + 8][k0 + tg + 4];
            }
            #pragma unroll
            for (int nt = 0; nt < 4; nt++) {
                int r = wn + nt * 8 + g;
                b[nt][0] = Bs[r][k0 + tg    ];
                b[nt][1] = Bs[r][k0 + tg + 4];
            }
            #pragma unroll
            for (int mt = 0; mt < 2; mt++)
                #pragma unroll
                for (int nt = 0; nt < 4; nt++)
                    mma_tf32(c[mt][nt], a[mt], b[nt]);
        }
        __syncthreads();
    }

    // epilogue: fold N into per-row partial scores, atomic into d_scores
    #pragma unroll
    for (int mt = 0; mt < 2; mt++) {
        float p0 = 0.f, p1 = 0.f;   // rows (wm+mt*16+g), (+8)
        #pragma unroll
        for (int nt = 0; nt < 4; nt++) {
            #pragma unroll
            for (int cc = 0; cc < 2; cc++) {
                int n = n0 + wn + nt * 8 + tg * 2 + cc;
                float tn = d_t[n];
                float vn = v[n];
                p0 += vn * tanhf(c[mt][nt][cc]     + tn);
                p1 += vn * tanhf(c[mt][nt][2 + cc] + tn);
            }
        }
        p0 += __shfl_xor_sync(0xffffffffu, p0, 1);
        p0 += __shfl_xor_sync(0xffffffffu, p0, 2);
        p1 += __shfl_xor_sync(0xffffffffu, p1, 1);
        p1 += __shfl_xor_sync(0xffffffffu, p1, 2);
        if (tg == 0) {
            srow[warp & 1][wm + mt * 16 + g    ] = p0;
            srow[warp & 1][wm + mt * 16 + g + 8] = p1;
        }
    }
    __syncthreads();
    if (tid < SBM)
        atomicAdd(&d_scores[m0 + tid], srow[0][tid] + srow[1][tid]);
}

// ---------------- K4: softmax (recomputed per block) + context slice ----------------
// grid (16 s-chunks, 4 e-chunks), 256 threads
__global__ void context_kernel(const float* __restrict__ enc, float* out_w)
{
    __shared__ float red[32];
    __shared__ float sw[128];       // this block's s-chunk weights
    __shared__ float smax, ssum;
    int tid = threadIdx.x;
    int lane = tid & 31, warp = tid >> 5;

    // softmax stats over all S (redundant per block, deterministic layout)
    float m = -1e30f;
    #pragma unroll
    for (int i = tid; i < S_LEN; i += 256) m = fmaxf(m, d_scores[i]);
    #pragma unroll
    for (int off = 16; off; off >>= 1) m = fmaxf(m, __shfl_xor_sync(0xffffffffu, m, off));
    if (lane == 0) red[warp] = m;
    __syncthreads();
    if (warp == 0) {
        m = (lane < 8) ? red[lane] : -1e30f;
        #pragma unroll
        for (int off = 4; off; off >>= 1) m = fmaxf(m, __shfl_xor_sync(0xffffffffu, m, off));
        if (lane == 0) smax = m;
    }
    __syncthreads();
    float mx = smax;
    float sum = 0.f;
    #pragma unroll
    for (int i = tid; i < S_LEN; i += 256) sum += expf(d_scores[i] - mx);
    #pragma unroll
    for (int off = 16; off; off >>= 1) sum += __shfl_xor_sync(0xffffffffu, sum, off);
    if (lane == 0) red[warp] = sum;
    __syncthreads();
    if (warp == 0) {
        sum = (lane < 8) ? red[lane] : 0.f;
        #pragma unroll
        for (int off = 4; off; off >>= 1) sum += __shfl_xor_sync(0xffffffffu, sum, off);
        if (lane == 0) ssum = sum;
    }
    __syncthreads();
    float inv = 1.0f / ssum;

    int s0 = blockIdx.x * 128;
    if (tid < 128) {
        float w = expf(d_scores[s0 + tid] - mx) * inv;
        sw[tid] = w;
        if (blockIdx.y == 0 && out_w) out_w[s0 + tid] = w;
    }
    __syncthreads();

    int e = blockIdx.y * 256 + tid;
    float a0 = 0.f, a1 = 0.f, a2 = 0.f, a3 = 0.f;
    #pragma unroll 4
    for (int s = 0; s < 128; s += 4) {
        a0 += sw[s    ] * enc[(size_t)(s0 + s    ) * E_DIM + e];
        a1 += sw[s + 1] * enc[(size_t)(s0 + s + 1) * E_DIM + e];
        a2 += sw[s + 2] * enc[(size_t)(s0 + s + 2) * E_DIM + e];
        a3 += sw[s + 3] * enc[(size_t)(s0 + s + 3) * E_DIM + e];
    }
    atomicAdd(&d_ctx[e], (a0 + a1) + (a2 + a3));
}

// ---------------- K5: x_t = tanh(W_ah @ [context; h] + b_ah) ----------------
__global__ void xt_kernel(const float* __restrict__ W_ah,
                          const float* __restrict__ b_ah,
                          float* out_xt)
{
    __shared__ float cat[EH];
    int tid = threadIdx.x;
    for (int i = tid; i < H_DIM; i += blockDim.x) {
        cat[i]          = d_ctx[i];
        cat[H_DIM + i]  = d_h[i];
    }
    __syncthreads();
    int warp = blockIdx.x * (blockDim.x >> 5) + (tid >> 5);
    int lane = tid & 31;
    if (warp >= H_DIM) return;
    const float* row = W_ah + (size_t)warp * EH;
    float acc = 0.f;
    #pragma unroll
    for (int k = lane * 4; k < EH; k += 128) {
        float4 w = *(const float4*)&row[k];
        float4 x = *(const float4*)&cat[k];
        acc += w.x*x.x + w.y*x.y + w.z*x.z + w.w*x.w;
    }
    #pragma unroll
    for (int off = 16; off; off >>= 1) acc += __shfl_down_sync(0xffffffffu, acc, off);
    if (lane == 0) {
        float x = tanhf(acc + b_ah[warp]);
        d_xt[warp] = x;
        if (out_xt) out_xt[warp] = x;
    }
}

// ---------------- K6: logits = W_out @ x_t + b_out, fused sumexp ----------------
__global__ void logits_kernel(const float* __restrict__ W_out,
                              const float* __restrict__ b_out)
{
    __shared__ float sx[H_DIM];
    __shared__ float wexp[8];
    int tid = threadIdx.x;
    for (int i = tid; i < H_DIM; i += 256) sx[i] = d_xt[i];
    __syncthreads();
    int warpl = tid >> 5, lane = tid & 31;
    int row = blockIdx.x * 8 + warpl;
    const float* wr = W_out + (size_t)row * H_DIM;
    float acc = 0.f;
    #pragma unroll
    for (int k = lane * 4; k < H_DIM; k += 128) {
        float4 w = *(const float4*)&wr[k];
        float4 x = *(const float4*)&sx[k];
        acc += w.x*x.x + w.y*x.y + w.z*x.z + w.w*x.w;
    }
    #pragma unroll
    for (int off = 16; off; off >>= 1) acc += __shfl_down_sync(0xffffffffu, acc, off);
    if (lane == 0) {
        float lg = acc + b_out[row];
        d_logits[row] = lg;
        wexp[warpl] = expf(lg);   // logits are O(1): exp without max is safe
    }
    __syncthreads();
    if (tid == 0) {
        float s = wexp[0];
        #pragma unroll
        for (int i = 1; i < 8; i++) s += wexp[i];
        atomicAdd(&d_sumexp, s);
    }
}

// ---------------- K7: out = logits - log(sumexp) ----------------
__global__ void writeout_kernel(float* __restrict__ out)
{
    float lse = logf(d_sumexp);
    int r = blockIdx.x * 256 + threadIdx.x;
    if (r < V_DIM) out[r] = d_logits[r] - lse;
}

// ---------------- launch ----------------
extern "C" void kernel_launch(void* const* d_in, const int* in_sizes, int n_in,
                              void* d_out, int out_size)
{
    const float* enc    = (const float*)d_in[0];
    const int*   word   = (const int*)  d_in[1];
    const float* lastc  = (const float*)d_in[2];
    const float* h0     = (const float*)d_in[3];
    const float* c0     = (const float*)d_in[4];
    const float* emb    = (const float*)d_in[5];
    const float* W_ih   = (const float*)d_in[6];
    const float* b_ih   = (const float*)d_in[7];
    const float* W_hh   = (const float*)d_in[8];
    const float* b_hh   = (const float*)d_in[9];
    const float* W_att  = (const float*)d_in[10];
    const float* b_att  = (const float*)d_in[11];
    const float* v      = (const float*)d_in[12];
    const float* W_ah   = (const float*)d_in[13];
    const float* b_ah   = (const float*)d_in[14];
    const float* W_out  = (const float*)d_in[15];
    const float* b_out  = (const float*)d_in[16];
    float* out = (float*)d_out;

    // flattened pytree: [output(V), h(H), c(H), x_t(H), w(S)]
    bool full = (out_size >= V_DIM + 3 * H_DIM + S_LEN);
    float* out_h  = full ? out + V_DIM              : nullptr;
    float* out_c  = full ? out + V_DIM + H_DIM      : nullptr;
    float* out_xt = full ? out + V_DIM + 2 * H_DIM  : nullptr;
    float* out_w  = full ? out + V_DIM + 3 * H_DIM  : nullptr;

    gates_kernel  <<<512, 256>>>(word, lastc, h0, emb, W_ih, b_ih, W_hh, b_hh);
    hterm_kernel  <<<128, 256>>>(W_att, b_att, c0, out_h, out_c);
    scores_kernel <<<dim3(H_DIM / SBN, S_LEN / SBM), 256>>>(enc, W_att, v);
    context_kernel<<<dim3(16, 4), 256>>>(enc, out_w);
    xt_kernel     <<<128, 256>>>(W_ah, b_ah, out_xt);
    logits_kernel <<<V_DIM / 8, 256>>>(W_out, b_out);
    writeout_kernel<<<125, 256>>>(out);
}

// round 7
// speedup vs baseline: 10.4744x; 1.0580x over previous
#include <cuda_runtime.h>
#include <math.h>
#include <stdint.h>

#define S_LEN 2048
#define E_DIM 1024
#define H_DIM 1024
#define V_DIM 32000
#define EH    2048   // E+H

// ---------------- scratch (no allocations allowed) ----------------
__device__ float d_gates[4 * H_DIM];
__device__ float d_h[H_DIM];
__device__ float d_t[H_DIM];           // W_att[:, :H] @ h + b_att
__device__ float d_scores[S_LEN];
__device__ float d_ctx[E_DIM];
__device__ float d_xt[H_DIM];
__device__ float d_logits[V_DIM];
__device__ float d_sumexp;

__device__ __forceinline__ float sigmoidf(float x) { return 1.0f / (1.0f + expf(-x)); }

__device__ __forceinline__ uint32_t f2tf32(float x) {
    uint32_t u;
    asm("cvt.rna.tf32.f32 %0, %1;" : "=r"(u) : "f"(x));
    return u;
}

// ---------------- K1: gate rows -> d_gates[4096] ----------------
__global__ void gates_kernel(const int* __restrict__ word_input,
                             const float* __restrict__ last_ctx,
                             const float* __restrict__ h0,
                             const float* __restrict__ emb,
                             const float* __restrict__ W_ih,
                             const float* __restrict__ b_ih,
                             const float* __restrict__ W_hh,
                             const float* __restrict__ b_hh)
{
    __shared__ float sin_[EH + H_DIM];  // [lstm_in(2048) | h_prev(1024)]
    int tid = threadIdx.x;
    int word = word_input[0];
    for (int i = tid; i < H_DIM; i += blockDim.x) {
        sin_[i]          = last_ctx[i];
        sin_[H_DIM + i]  = emb[(size_t)word * E_DIM + i];
        sin_[EH + i]     = h0[i];
    }
    __syncthreads();

    int r = blockIdx.x * 8 + (tid >> 5);   // gate row 0..4095
    int lane = tid & 31;

    const float* wrow = W_ih + (size_t)r * EH;
    float acc = 0.f;
    #pragma unroll
    for (int k = lane * 4; k < EH; k += 128) {
        float4 w = *(const float4*)&wrow[k];
        float4 x = *(const float4*)&sin_[k];
        acc += w.x*x.x + w.y*x.y + w.z*x.z + w.w*x.w;
    }
    const float* hrow = W_hh + (size_t)r * H_DIM;
    #pragma unroll
    for (int k = lane * 4; k < H_DIM; k += 128) {
        float4 w = *(const float4*)&hrow[k];
        float4 x = *(const float4*)&sin_[EH + k];
        acc += w.x*x.x + w.y*x.y + w.z*x.z + w.w*x.w;
    }
    #pragma unroll
    for (int off = 16; off; off >>= 1) acc += __shfl_down_sync(0xffffffffu, acc, off);
    if (lane == 0) d_gates[r] = acc + b_ih[r] + b_hh[r];
}

// ---------------- K2: h from gates + t = W_att[:, :H].h + b_att (+ zero scratch) ----------------
__global__ void hterm_kernel(const float* __restrict__ W_att,
                             const float* __restrict__ b_att,
                             const float* __restrict__ c0,
                             float* out_h, float* out_c)
{
    __shared__ float sh[H_DIM];
    int tid = threadIdx.x;
    for (int j = tid; j < H_DIM; j += blockDim.x) {
        float iv = sigmoidf(d_gates[j]);
        float fv = sigmoidf(d_gates[j +   H_DIM]);
        float gv = tanhf  (d_gates[j + 2*H_DIM]);
        float ov = sigmoidf(d_gates[j + 3*H_DIM]);
        float cv = fv * c0[j] + iv * gv;
        float hv = ov * tanhf(cv);
        sh[j] = hv;
        if (blockIdx.x == 0) {
            d_h[j] = hv;
            d_ctx[j] = 0.f;
            if (out_h) out_h[j] = hv;
            if (out_c) out_c[j] = cv;
        }
    }
    if (blockIdx.x == 1) {
        for (int i = tid; i < S_LEN; i += blockDim.x) d_scores[i] = 0.f;
        if (tid == 0) d_sumexp = 0.f;
    }
    __syncthreads();

    int warp = blockIdx.x * (blockDim.x >> 5) + (tid >> 5);
    int lane = tid & 31;
    if (warp >= H_DIM) return;
    const float* row = W_att + (size_t)warp * EH;
    float acc = 0.f;
    #pragma unroll
    for (int k = lane * 4; k < H_DIM; k += 128) {
        float4 w = *(const float4*)&row[k];
        float4 x = *(const float4*)&sh[k];
        acc += w.x*x.x + w.y*x.y + w.z*x.z + w.w*x.w;
    }
    #pragma unroll
    for (int off = 16; off; off >>= 1) acc += __shfl_down_sync(0xffffffffu, acc, off);
    if (lane == 0) d_t[warp] = acc + b_att[warp];
}

// ---------------- K3: scores GEMM via tf32 mma.sync (128x128 tiles) ----------------
#define SBM 128
#define SBN 128
#define SBK 32
#define SKPAD 4
#define NKI (E_DIM / SBK)

__device__ __forceinline__ void mma_tf32(float* c, const uint32_t* a, const uint32_t* b) {
    asm volatile(
        "mma.sync.aligned.m16n8k8.row.col.f32.tf32.tf32.f32 "
        "{%0,%1,%2,%3}, {%4,%5,%6,%7}, {%8,%9}, {%0,%1,%2,%3};"
        : "+f"(c[0]), "+f"(c[1]), "+f"(c[2]), "+f"(c[3])
        : "r"(a[0]), "r"(a[1]), "r"(a[2]), "r"(a[3]), "r"(b[0]), "r"(b[1]));
}

__global__ __launch_bounds__(256, 1)
void scores_kernel(const float* __restrict__ enc,
                   const float* __restrict__ W_att,
                   const float* __restrict__ v)
{
    __shared__ uint32_t As[SBM][SBK + SKPAD];   // tf32 bits
    __shared__ uint32_t Bs[SBN][SBK + SKPAD];
    __shared__ float srow[2][SBM];

    int tid  = threadIdx.x;
    int warp = tid >> 5, lane = tid & 31;
    int g = lane >> 2, tg = lane & 3;
    int m0 = blockIdx.y * SBM;
    int n0 = blockIdx.x * SBN;
    int wm = (warp >> 1) * 32;      // warp M offset (0,32,64,96)
    int wn = (warp & 1) * 64;       // warp N offset (0,64)

    float c[2][8][4];
    #pragma unroll
    for (int mt = 0; mt < 2; mt++)
        #pragma unroll
        for (int nt = 0; nt < 8; nt++)
            #pragma unroll
            for (int i = 0; i < 4; i++) c[mt][nt][i] = 0.f;

    int lrow = tid >> 3;            // 0..31
    int lcol = (tid & 7) * 4;       // 0,4,...,28

    const float* aptr = enc   + (size_t)(m0 + lrow) * E_DIM + lcol;
    const float* bptr = W_att + (size_t)(n0 + lrow) * EH + H_DIM + lcol;

    float4 ra[4], rb[4];
    #pragma unroll
    for (int i = 0; i < 4; i++) ra[i] = *(const float4*)(aptr + (size_t)i * 32 * E_DIM);
    #pragma unroll
    for (int i = 0; i < 4; i++) rb[i] = *(const float4*)(bptr + (size_t)i * 32 * EH);

    for (int kt_i = 0; kt_i < NKI; kt_i++) {
        #pragma unroll
        for (int i = 0; i < 4; i++) {
            int r = lrow + i * 32;
            As[r][lcol + 0] = f2tf32(ra[i].x);
            As[r][lcol + 1] = f2tf32(ra[i].y);
            As[r][lcol + 2] = f2tf32(ra[i].z);
            As[r][lcol + 3] = f2tf32(ra[i].w);
            Bs[r][lcol + 0] = f2tf32(rb[i].x);
            Bs[r][lcol + 1] = f2tf32(rb[i].y);
            Bs[r][lcol + 2] = f2tf32(rb[i].z);
            Bs[r][lcol + 3] = f2tf32(rb[i].w);
        }
        __syncthreads();

        if (kt_i + 1 < NKI) {
            const float* an = aptr + (size_t)(kt_i + 1) * SBK;
            const float* bn = bptr + (size_t)(kt_i + 1) * SBK;
            #pragma unroll
            for (int i = 0; i < 4; i++) ra[i] = *(const float4*)(an + (size_t)i * 32 * E_DIM);
            #pragma unroll
            for (int i = 0; i < 4; i++) rb[i] = *(const float4*)(bn + (size_t)i * 32 * EH);
        }

        #pragma unroll
        for (int ks = 0; ks < 4; ks++) {
            int k0 = ks * 8;
            uint32_t a[2][4], b[8][2];
            #pragma unroll
            for (int mt = 0; mt < 2; mt++) {
                int r = wm + mt * 16 + g;
                a[mt][0] = As[r    ][k0 + tg    ];
                a[mt][1] = As[r + 8][k0 + tg    ];
                a[mt][2] = As[r    ][k0 + tg + 4];
                a[mt][3] = As[r + 8][k0 + tg + 4];
            }
            #pragma unroll
            for (int nt = 0; nt < 8; nt++) {
                int r = wn + nt * 8 + g;
                b[nt][0] = Bs[r][k0 + tg    ];
                b[nt][1] = Bs[r][k0 + tg + 4];
            }
            #pragma unroll
            for (int mt = 0; mt < 2; mt++)
                #pragma unroll
                for (int nt = 0; nt < 8; nt++)
                    mma_tf32(c[mt][nt], a[mt], b[nt]);
        }
        __syncthreads();
    }

    // epilogue: fold this block's 128 N-cols into per-row partials, atomic into d_scores
    #pragma unroll
    for (int mt = 0; mt < 2; mt++) {
        float p0 = 0.f, p1 = 0.f;   // rows (wm+mt*16+g), (+8)
        #pragma unroll
        for (int nt = 0; nt < 8; nt++) {
            #pragma unroll
            for (int cc = 0; cc < 2; cc++) {
                int n = n0 + wn + nt * 8 + tg * 2 + cc;
                float tn = d_t[n];
                float vn = v[n];
                p0 += vn * tanhf(c[mt][nt][cc]     + tn);
                p1 += vn * tanhf(c[mt][nt][2 + cc] + tn);
            }
        }
        p0 += __shfl_xor_sync(0xffffffffu, p0, 1);
        p0 += __shfl_xor_sync(0xffffffffu, p0, 2);
        p1 += __shfl_xor_sync(0xffffffffu, p1, 1);
        p1 += __shfl_xor_sync(0xffffffffu, p1, 2);
        if (tg == 0) {
            srow[warp & 1][wm + mt * 16 + g    ] = p0;
            srow[warp & 1][wm + mt * 16 + g + 8] = p1;
        }
    }
    __syncthreads();
    if (tid < SBM)
        atomicAdd(&d_scores[m0 + tid], srow[0][tid] + srow[1][tid]);
}

// ---------------- K4: softmax (recomputed per block) + context slice ----------------
// grid (64 s-chunks of 32, 4 e-chunks of 256), 256 threads
__global__ void context_kernel(const float* __restrict__ enc, float* out_w)
{
    __shared__ float red[32];
    __shared__ float sw[32];        // this block's s-chunk weights
    __shared__ float smax, ssum;
    int tid = threadIdx.x;
    int lane = tid & 31, warp = tid >> 5;

    // softmax stats over all S (redundant per block, deterministic)
    float m = -1e30f;
    #pragma unroll
    for (int i = tid; i < S_LEN; i += 256) m = fmaxf(m, d_scores[i]);
    #pragma unroll
    for (int off = 16; off; off >>= 1) m = fmaxf(m, __shfl_xor_sync(0xffffffffu, m, off));
    if (lane == 0) red[warp] = m;
    __syncthreads();
    if (warp == 0) {
        m = (lane < 8) ? red[lane] : -1e30f;
        #pragma unroll
        for (int off = 4; off; off >>= 1) m = fmaxf(m, __shfl_xor_sync(0xffffffffu, m, off));
        if (lane == 0) smax = m;
    }
    __syncthreads();
    float mx = smax;
    float sum = 0.f;
    #pragma unroll
    for (int i = tid; i < S_LEN; i += 256) sum += expf(d_scores[i] - mx);
    #pragma unroll
    for (int off = 16; off; off >>= 1) sum += __shfl_xor_sync(0xffffffffu, sum, off);
    if (lane == 0) red[warp] = sum;
    __syncthreads();
    if (warp == 0) {
        sum = (lane < 8) ? red[lane] : 0.f;
        #pragma unroll
        for (int off = 4; off; off >>= 1) sum += __shfl_xor_sync(0xffffffffu, sum, off);
        if (lane == 0) ssum = sum;
    }
    __syncthreads();
    float inv = 1.0f / ssum;

    int s0 = blockIdx.x * 32;
    if (tid < 32) {
        float w = expf(d_scores[s0 + tid] - mx) * inv;
        sw[tid] = w;
        if (blockIdx.y == 0 && out_w) out_w[s0 + tid] = w;
    }
    __syncthreads();

    int e = blockIdx.y * 256 + tid;
    float a0 = 0.f, a1 = 0.f, a2 = 0.f, a3 = 0.f;
    #pragma unroll
    for (int s = 0; s < 32; s += 4) {
        a0 += sw[s    ] * enc[(size_t)(s0 + s    ) * E_DIM + e];
        a1 += sw[s + 1] * enc[(size_t)(s0 + s + 1) * E_DIM + e];
        a2 += sw[s + 2] * enc[(size_t)(s0 + s + 2) * E_DIM + e];
        a3 += sw[s + 3] * enc[(size_t)(s0 + s + 3) * E_DIM + e];
    }
    atomicAdd(&d_ctx[e], (a0 + a1) + (a2 + a3));
}

// ---------------- K5: x_t = tanh(W_ah @ [context; h] + b_ah) ----------------
__global__ void xt_kernel(const float* __restrict__ W_ah,
                          const float* __restrict__ b_ah,
                          float* out_xt)
{
    __shared__ float cat[EH];
    int tid = threadIdx.x;
    for (int i = tid; i < H_DIM; i += blockDim.x) {
        cat[i]          = d_ctx[i];
        cat[H_DIM + i]  = d_h[i];
    }
    __syncthreads();
    int warp = blockIdx.x * (blockDim.x >> 5) + (tid >> 5);
    int lane = tid & 31;
    if (warp >= H_DIM) return;
    const float* row = W_ah + (size_t)warp * EH;
    float acc = 0.f;
    #pragma unroll
    for (int k = lane * 4; k < EH; k += 128) {
        float4 w = *(const float4*)&row[k];
        float4 x = *(const float4*)&cat[k];
        acc += w.x*x.x + w.y*x.y + w.z*x.z + w.w*x.w;
    }
    #pragma unroll
    for (int off = 16; off; off >>= 1) acc += __shfl_down_sync(0xffffffffu, acc, off);
    if (lane == 0) {
        float x = tanhf(acc + b_ah[warp]);
        d_xt[warp] = x;
        if (out_xt) out_xt[warp] = x;
    }
}

// ---------------- K6: logits = W_out @ x_t + b_out, fused sumexp ----------------
__global__ void logits_kernel(const float* __restrict__ W_out,
                              const float* __restrict__ b_out)
{
    __shared__ float sx[H_DIM];
    __shared__ float wexp[8];
    int tid = threadIdx.x;
    for (int i = tid; i < H_DIM; i += 256) sx[i] = d_xt[i];
    __syncthreads();
    int warpl = tid >> 5, lane = tid & 31;
    int row = blockIdx.x * 8 + warpl;
    const float* wr = W_out + (size_t)row * H_DIM;
    float acc = 0.f;
    #pragma unroll
    for (int k = lane * 4; k < H_DIM; k += 128) {
        float4 w = *(const float4*)&wr[k];
        float4 x = *(const float4*)&sx[k];
        acc += w.x*x.x + w.y*x.y + w.z*x.z + w.w*x.w;
    }
    #pragma unroll
    for (int off = 16; off; off >>= 1) acc += __shfl_down_sync(0xffffffffu, acc, off);
    if (lane == 0) {
        float lg = acc + b_out[row];
        d_logits[row] = lg;
        wexp[warpl] = expf(lg);   // logits are O(1): exp without max is safe
    }
    __syncthreads();
    if (tid == 0) {
        float s = wexp[0];
        #pragma unroll
        for (int i = 1; i < 8; i++) s += wexp[i];
        atomicAdd(&d_sumexp, s);
    }
}

// ---------------- K7: out = logits - log(sumexp) ----------------
__global__ void writeout_kernel(float* __restrict__ out)
{
    float lse = logf(d_sumexp);
    int r = blockIdx.x * 256 + threadIdx.x;
    if (r < V_DIM) out[r] = d_logits[r] - lse;
}

// ---------------- launch ----------------
extern "C" void kernel_launch(void* const* d_in, const int* in_sizes, int n_in,
                              void* d_out, int out_size)
{
    const float* enc    = (const float*)d_in[0];
    const int*   word   = (const int*)  d_in[1];
    const float* lastc  = (const float*)d_in[2];
    const float* h0     = (const float*)d_in[3];
    const float* c0     = (const float*)d_in[4];
    const float* emb    = (const float*)d_in[5];
    const float* W_ih   = (const float*)d_in[6];
    const float* b_ih   = (const float*)d_in[7];
    const float* W_hh   = (const float*)d_in[8];
    const float* b_hh   = (const float*)d_in[9];
    const float* W_att  = (const float*)d_in[10];
    const float* b_att  = (const float*)d_in[11];
    const float* v      = (const float*)d_in[12];
    const float* W_ah   = (const float*)d_in[13];
    const float* b_ah   = (const float*)d_in[14];
    const float* W_out  = (const float*)d_in[15];
    const float* b_out  = (const float*)d_in[16];
    float* out = (float*)d_out;

    // flattened pytree: [output(V), h(H), c(H), x_t(H), w(S)]
    bool full = (out_size >= V_DIM + 3 * H_DIM + S_LEN);
    float* out_h  = full ? out + V_DIM              : nullptr;
    float* out_c  = full ? out + V_DIM + H_DIM      : nullptr;
    float* out_xt = full ? out + V_DIM + 2 * H_DIM  : nullptr;
    float* out_w  = full ? out + V_DIM + 3 * H_DIM  : nullptr;

    gates_kernel  <<<512, 256>>>(word, lastc, h0, emb, W_ih, b_ih, W_hh, b_hh);
    hterm_kernel  <<<128, 256>>>(W_att, b_att, c0, out_h, out_c);
    scores_kernel <<<dim3(H_DIM / SBN, S_LEN / SBM), 256>>>(enc, W_att, v);
    context_kernel<<<dim3(64, 4), 256>>>(enc, out_w);
    xt_kernel     <<<128, 256>>>(W_ah, b_ah, out_xt);
    logits_kernel <<<V_DIM / 8, 256>>>(W_out, b_out);
    writeout_kernel<<<125, 256>>>(out);
}

// round 8
// speedup vs baseline: 10.4778x; 1.0003x over previous
#include <cuda_runtime.h>
#include <math.h>
#include <stdint.h>

#define S_LEN 2048
#define E_DIM 1024
#define H_DIM 1024
#define V_DIM 32000
#define EH    2048   // E+H

// ---------------- scratch (no allocations allowed) ----------------
__device__ float d_gates[4 * H_DIM];
__device__ float d_h[H_DIM];
__device__ float d_t[H_DIM];           // W_att[:, :H] @ h + b_att
__device__ float d_scores[S_LEN];
__device__ float d_ctx[E_DIM];
__device__ float d_xt[H_DIM];
__device__ float d_logits[V_DIM];
__device__ float d_sumexp;
__device__ float d_smax, d_sinv;       // softmax stats (computed by last scores block)
__device__ unsigned d_cnt;             // scores completion ticket

__device__ __forceinline__ float sigmoidf(float x) { return 1.0f / (1.0f + expf(-x)); }

__device__ __forceinline__ uint32_t f2tf32(float x) {
    uint32_t u;
    asm("cvt.rna.tf32.f32 %0, %1;" : "=r"(u) : "f"(x));
    return u;
}

// ---------------- K1: gate rows -> d_gates[4096] ----------------
__global__ void gates_kernel(const int* __restrict__ word_input,
                             const float* __restrict__ last_ctx,
                             const float* __restrict__ h0,
                             const float* __restrict__ emb,
                             const float* __restrict__ W_ih,
                             const float* __restrict__ b_ih,
                             const float* __restrict__ W_hh,
                             const float* __restrict__ b_hh)
{
    __shared__ float sin_[EH + H_DIM];  // [lstm_in(2048) | h_prev(1024)]
    int tid = threadIdx.x;
    int word = word_input[0];
    for (int i = tid; i < H_DIM; i += blockDim.x) {
        sin_[i]          = last_ctx[i];
        sin_[H_DIM + i]  = emb[(size_t)word * E_DIM + i];
        sin_[EH + i]     = h0[i];
    }
    __syncthreads();

    int r = blockIdx.x * 8 + (tid >> 5);   // gate row 0..4095
    int lane = tid & 31;

    const float* wrow = W_ih + (size_t)r * EH;
    float acc = 0.f;
    #pragma unroll
    for (int k = lane * 4; k < EH; k += 128) {
        float4 w = *(const float4*)&wrow[k];
        float4 x = *(const float4*)&sin_[k];
        acc += w.x*x.x + w.y*x.y + w.z*x.z + w.w*x.w;
    }
    const float* hrow = W_hh + (size_t)r * H_DIM;
    #pragma unroll
    for (int k = lane * 4; k < H_DIM; k += 128) {
        float4 w = *(const float4*)&hrow[k];
        float4 x = *(const float4*)&sin_[EH + k];
        acc += w.x*x.x + w.y*x.y + w.z*x.z + w.w*x.w;
    }
    #pragma unroll
    for (int off = 16; off; off >>= 1) acc += __shfl_down_sync(0xffffffffu, acc, off);
    if (lane == 0) d_gates[r] = acc + b_ih[r] + b_hh[r];
}

// ---------------- K2: h from gates + t = W_att[:, :H].h + b_att (+ zero scratch) ----------------
__global__ void hterm_kernel(const float* __restrict__ W_att,
                             const float* __restrict__ b_att,
                             const float* __restrict__ c0,
                             float* out_h, float* out_c)
{
    __shared__ float sh[H_DIM];
    int tid = threadIdx.x;
    for (int j = tid; j < H_DIM; j += blockDim.x) {
        float iv = sigmoidf(d_gates[j]);
        float fv = sigmoidf(d_gates[j +   H_DIM]);
        float gv = tanhf  (d_gates[j + 2*H_DIM]);
        float ov = sigmoidf(d_gates[j + 3*H_DIM]);
        float cv = fv * c0[j] + iv * gv;
        float hv = ov * tanhf(cv);
        sh[j] = hv;
        if (blockIdx.x == 0) {
            d_h[j] = hv;
            d_ctx[j] = 0.f;
            if (out_h) out_h[j] = hv;
            if (out_c) out_c[j] = cv;
        }
    }
    if (blockIdx.x == 1) {
        for (int i = tid; i < S_LEN; i += blockDim.x) d_scores[i] = 0.f;
        if (tid == 0) { d_sumexp = 0.f; d_cnt = 0u; }
    }
    __syncthreads();

    int warp = blockIdx.x * (blockDim.x >> 5) + (tid >> 5);
    int lane = tid & 31;
    if (warp >= H_DIM) return;
    const float* row = W_att + (size_t)warp * EH;
    float acc = 0.f;
    #pragma unroll
    for (int k = lane * 4; k < H_DIM; k += 128) {
        float4 w = *(const float4*)&row[k];
        float4 x = *(const float4*)&sh[k];
        acc += w.x*x.x + w.y*x.y + w.z*x.z + w.w*x.w;
    }
    #pragma unroll
    for (int off = 16; off; off >>= 1) acc += __shfl_down_sync(0xffffffffu, acc, off);
    if (lane == 0) d_t[warp] = acc + b_att[warp];
}

// ---------------- K3: scores GEMM via tf32 mma.sync (128x128 tiles) ----------------
#define SBM 128
#define SBN 128
#define SBK 32
#define SKPAD 4
#define NKI (E_DIM / SBK)
#define SC_BLOCKS ((H_DIM / SBN) * (S_LEN / SBM))   // 128

__device__ __forceinline__ void mma_tf32(float* c, const uint32_t* a, const uint32_t* b) {
    asm volatile(
        "mma.sync.aligned.m16n8k8.row.col.f32.tf32.tf32.f32 "
        "{%0,%1,%2,%3}, {%4,%5,%6,%7}, {%8,%9}, {%0,%1,%2,%3};"
        : "+f"(c[0]), "+f"(c[1]), "+f"(c[2]), "+f"(c[3])
        : "r"(a[0]), "r"(a[1]), "r"(a[2]), "r"(a[3]), "r"(b[0]), "r"(b[1]));
}

__global__ __launch_bounds__(256, 1)
void scores_kernel(const float* __restrict__ enc,
                   const float* __restrict__ W_att,
                   const float* __restrict__ v)
{
    __shared__ uint32_t As[SBM][SBK + SKPAD];   // tf32 bits
    __shared__ uint32_t Bs[SBN][SBK + SKPAD];
    __shared__ float srow[2][SBM];
    __shared__ float red[8];
    __shared__ bool amLast;

    int tid  = threadIdx.x;
    int warp = tid >> 5, lane = tid & 31;
    int g = lane >> 2, tg = lane & 3;
    int m0 = blockIdx.y * SBM;
    int n0 = blockIdx.x * SBN;
    int wm = (warp >> 1) * 32;      // warp M offset (0,32,64,96)
    int wn = (warp & 1) * 64;       // warp N offset (0,64)

    float c[2][8][4];
    #pragma unroll
    for (int mt = 0; mt < 2; mt++)
        #pragma unroll
        for (int nt = 0; nt < 8; nt++)
            #pragma unroll
            for (int i = 0; i < 4; i++) c[mt][nt][i] = 0.f;

    int lrow = tid >> 3;            // 0..31
    int lcol = (tid & 7) * 4;       // 0,4,...,28

    const float* aptr = enc   + (size_t)(m0 + lrow) * E_DIM + lcol;
    const float* bptr = W_att + (size_t)(n0 + lrow) * EH + H_DIM + lcol;

    float4 ra[4], rb[4];
    #pragma unroll
    for (int i = 0; i < 4; i++) ra[i] = *(const float4*)(aptr + (size_t)i * 32 * E_DIM);
    #pragma unroll
    for (int i = 0; i < 4; i++) rb[i] = *(const float4*)(bptr + (size_t)i * 32 * EH);

    for (int kt_i = 0; kt_i < NKI; kt_i++) {
        #pragma unroll
        for (int i = 0; i < 4; i++) {
            int r = lrow + i * 32;
            As[r][lcol + 0] = f2tf32(ra[i].x);
            As[r][lcol + 1] = f2tf32(ra[i].y);
            As[r][lcol + 2] = f2tf32(ra[i].z);
            As[r][lcol + 3] = f2tf32(ra[i].w);
            Bs[r][lcol + 0] = f2tf32(rb[i].x);
            Bs[r][lcol + 1] = f2tf32(rb[i].y);
            Bs[r][lcol + 2] = f2tf32(rb[i].z);
            Bs[r][lcol + 3] = f2tf32(rb[i].w);
        }
        __syncthreads();

        if (kt_i + 1 < NKI) {
            const float* an = aptr + (size_t)(kt_i + 1) * SBK;
            const float* bn = bptr + (size_t)(kt_i + 1) * SBK;
            #pragma unroll
            for (int i = 0; i < 4; i++) ra[i] = *(const float4*)(an + (size_t)i * 32 * E_DIM);
            #pragma unroll
            for (int i = 0; i < 4; i++) rb[i] = *(const float4*)(bn + (size_t)i * 32 * EH);
        }

        #pragma unroll
        for (int ks = 0; ks < 4; ks++) {
            int k0 = ks * 8;
            uint32_t a[2][4], b[8][2];
            #pragma unroll
            for (int mt = 0; mt < 2; mt++) {
                int r = wm + mt * 16 + g;
                a[mt][0] = As[r    ][k0 + tg    ];
                a[mt][1] = As[r + 8][k0 + tg    ];
                a[mt][2] = As[r    ][k0 + tg + 4];
                a[mt][3] = As[r + 8][k0 + tg + 4];
            }
            #pragma unroll
            for (int nt = 0; nt < 8; nt++) {
                int r = wn + nt * 8 + g;
                b[nt][0] = Bs[r][k0 + tg    ];
                b[nt][1] = Bs[r][k0 + tg + 4];
            }
            #pragma unroll
            for (int mt = 0; mt < 2; mt++)
                #pragma unroll
                for (int nt = 0; nt < 8; nt++)
                    mma_tf32(c[mt][nt], a[mt], b[nt]);
        }
        __syncthreads();
    }

    // epilogue: fold this block's 128 N-cols into per-row partials, atomic into d_scores
    #pragma unroll
    for (int mt = 0; mt < 2; mt++) {
        float p0 = 0.f, p1 = 0.f;   // rows (wm+mt*16+g), (+8)
        #pragma unroll
        for (int nt = 0; nt < 8; nt++) {
            #pragma unroll
            for (int cc = 0; cc < 2; cc++) {
                int n = n0 + wn + nt * 8 + tg * 2 + cc;
                float tn = d_t[n];
                float vn = v[n];
                p0 += vn * tanhf(c[mt][nt][cc]     + tn);
                p1 += vn * tanhf(c[mt][nt][2 + cc] + tn);
            }
        }
        p0 += __shfl_xor_sync(0xffffffffu, p0, 1);
        p0 += __shfl_xor_sync(0xffffffffu, p0, 2);
        p1 += __shfl_xor_sync(0xffffffffu, p1, 1);
        p1 += __shfl_xor_sync(0xffffffffu, p1, 2);
        if (tg == 0) {
            srow[warp & 1][wm + mt * 16 + g    ] = p0;
            srow[warp & 1][wm + mt * 16 + g + 8] = p1;
        }
    }
    __syncthreads();
    if (tid < SBM)
        atomicAdd(&d_scores[m0 + tid], srow[0][tid] + srow[1][tid]);

    // last block computes the softmax stats once
    __threadfence();
    __syncthreads();
    if (tid == 0) amLast = (atomicAdd(&d_cnt, 1u) == SC_BLOCKS - 1);
    __syncthreads();
    if (amLast) {
        float m = -1e30f;
        #pragma unroll
        for (int i = tid; i < S_LEN; i += 256) m = fmaxf(m, d_scores[i]);
        #pragma unroll
        for (int off = 16; off; off >>= 1) m = fmaxf(m, __shfl_xor_sync(0xffffffffu, m, off));
        if (lane == 0) red[warp] = m;
        __syncthreads();
        float mx;
        {
            float t0 = red[0];
            #pragma unroll
            for (int i = 1; i < 8; i++) t0 = fmaxf(t0, red[i]);
            mx = t0;
        }
        float sum = 0.f;
        #pragma unroll
        for (int i = tid; i < S_LEN; i += 256) sum += expf(d_scores[i] - mx);
        #pragma unroll
        for (int off = 16; off; off >>= 1) sum += __shfl_xor_sync(0xffffffffu, sum, off);
        __syncthreads();           // red[] reuse
        if (lane == 0) red[warp] = sum;
        __syncthreads();
        if (tid == 0) {
            float s = red[0];
            #pragma unroll
            for (int i = 1; i < 8; i++) s += red[i];
            d_smax = mx;
            d_sinv = 1.0f / s;
        }
    }
}

// ---------------- K4: context slice (stats precomputed) ----------------
// grid (128 s-chunks of 16, 4 e-chunks of 256), 256 threads
__global__ void context_kernel(const float* __restrict__ enc, float* out_w)
{
    __shared__ float sw[16];
    int tid = threadIdx.x;
    float mx = d_smax, inv = d_sinv;

    int s0 = blockIdx.x * 16;
    if (tid < 16) {
        float w = expf(d_scores[s0 + tid] - mx) * inv;
        sw[tid] = w;
        if (blockIdx.y == 0 && out_w) out_w[s0 + tid] = w;
    }
    __syncthreads();

    int e = blockIdx.y * 256 + tid;
    float a0 = 0.f, a1 = 0.f, a2 = 0.f, a3 = 0.f;
    #pragma unroll
    for (int s = 0; s < 16; s += 4) {
        a0 += sw[s    ] * enc[(size_t)(s0 + s    ) * E_DIM + e];
        a1 += sw[s + 1] * enc[(size_t)(s0 + s + 1) * E_DIM + e];
        a2 += sw[s + 2] * enc[(size_t)(s0 + s + 2) * E_DIM + e];
        a3 += sw[s + 3] * enc[(size_t)(s0 + s + 3) * E_DIM + e];
    }
    atomicAdd(&d_ctx[e], (a0 + a1) + (a2 + a3));
}

// ---------------- K5: x_t = tanh(W_ah @ [context; h] + b_ah) ----------------
__global__ void xt_kernel(const float* __restrict__ W_ah,
                          const float* __restrict__ b_ah,
                          float* out_xt)
{
    __shared__ float cat[EH];
    int tid = threadIdx.x;
    for (int i = tid; i < H_DIM; i += blockDim.x) {
        cat[i]          = d_ctx[i];
        cat[H_DIM + i]  = d_h[i];
    }
    __syncthreads();
    int warp = blockIdx.x * (blockDim.x >> 5) + (tid >> 5);
    int lane = tid & 31;
    if (warp >= H_DIM) return;
    const float* row = W_ah + (size_t)warp * EH;
    float acc = 0.f;
    #pragma unroll
    for (int k = lane * 4; k < EH; k += 128) {
        float4 w = *(const float4*)&row[k];
        float4 x = *(const float4*)&cat[k];
        acc += w.x*x.x + w.y*x.y + w.z*x.z + w.w*x.w;
    }
    #pragma unroll
    for (int off = 16; off; off >>= 1) acc += __shfl_down_sync(0xffffffffu, acc, off);
    if (lane == 0) {
        float x = tanhf(acc + b_ah[warp]);
        d_xt[warp] = x;
        if (out_xt) out_xt[warp] = x;
    }
}

// ---------------- K6: logits = W_out @ x_t + b_out, fused sumexp ----------------
__global__ void logits_kernel(const float* __restrict__ W_out,
                              const float* __restrict__ b_out)
{
    __shared__ float sx[H_DIM];
    __shared__ float wexp[8];
    int tid = threadIdx.x;
    for (int i = tid; i < H_DIM; i += 256) sx[i] = d_xt[i];
    __syncthreads();
    int warpl = tid >> 5, lane = tid & 31;
    int row = blockIdx.x * 8 + warpl;
    const float* wr = W_out + (size_t)row * H_DIM;
    float acc = 0.f;
    #pragma unroll
    for (int k = lane * 4; k < H_DIM; k += 128) {
        float4 w = *(const float4*)&wr[k];
        float4 x = *(const float4*)&sx[k];
        acc += w.x*x.x + w.y*x.y + w.z*x.z + w.w*x.w;
    }
    #pragma unroll
    for (int off = 16; off; off >>= 1) acc += __shfl_down_sync(0xffffffffu, acc, off);
    if (lane == 0) {
        float lg = acc + b_out[row];
        d_logits[row] = lg;
        wexp[warpl] = expf(lg);   // logits are O(1): exp without max is safe
    }
    __syncthreads();
    if (tid == 0) {
        float s = wexp[0];
        #pragma unroll
        for (int i = 1; i < 8; i++) s += wexp[i];
        atomicAdd(&d_sumexp, s);
    }
}

// ---------------- K7: out = logits - log(sumexp) ----------------
__global__ void writeout_kernel(float* __restrict__ out)
{
    float lse = logf(d_sumexp);
    int r = blockIdx.x * 256 + threadIdx.x;
    if (r < V_DIM) out[r] = d_logits[r] - lse;
}

// ---------------- launch ----------------
extern "C" void kernel_launch(void* const* d_in, const int* in_sizes, int n_in,
                              void* d_out, int out_size)
{
    const float* enc    = (const float*)d_in[0];
    const int*   word   = (const int*)  d_in[1];
    const float* lastc  = (const float*)d_in[2];
    const float* h0     = (const float*)d_in[3];
    const float* c0     = (const float*)d_in[4];
    const float* emb    = (const float*)d_in[5];
    const float* W_ih   = (const float*)d_in[6];
    const float* b_ih   = (const float*)d_in[7];
    const float* W_hh   = (const float*)d_in[8];
    const float* b_hh   = (const float*)d_in[9];
    const float* W_att  = (const float*)d_in[10];
    const float* b_att  = (const float*)d_in[11];
    const float* v      = (const float*)d_in[12];
    const float* W_ah   = (const float*)d_in[13];
    const float* b_ah   = (const float*)d_in[14];
    const float* W_out  = (const float*)d_in[15];
    const float* b_out  = (const float*)d_in[16];
    float* out = (float*)d_out;

    // flattened pytree: [output(V), h(H), c(H), x_t(H), w(S)]
    bool full = (out_size >= V_DIM + 3 * H_DIM + S_LEN);
    float* out_h  = full ? out + V_DIM              : nullptr;
    float* out_c  = full ? out + V_DIM + H_DIM      : nullptr;
    float* out_xt = full ? out + V_DIM + 2 * H_DIM  : nullptr;
    float* out_w  = full ? out + V_DIM + 3 * H_DIM  : nullptr;

    gates_kernel  <<<512, 256>>>(word, lastc, h0, emb, W_ih, b_ih, W_hh, b_hh);
    hterm_kernel  <<<128, 256>>>(W_att, b_att, c0, out_h, out_c);
    scores_kernel <<<dim3(H_DIM / SBN, S_LEN / SBM), 256>>>(enc, W_att, v);
    context_kernel<<<dim3(128, 4), 256>>>(enc, out_w);
    xt_kernel     <<<128, 256>>>(W_ah, b_ah, out_xt);
    logits_kernel <<<V_DIM / 8, 256>>>(W_out, b_out);
    writeout_kernel<<<125, 256>>>(out);
}